// round 10
// baseline (speedup 1.0000x reference)
#include <cuda_runtime.h>
#include <cuda_bf16.h>
#include <math.h>
#include <stdint.h>

// ----------------------------------------------------------------------------
// SimpleGAT R10: tf32 split moved to smem-store time (split once per CTA,
// inner loop = pure LDS+MMA). Tile 64x128, BK=16, 8 warps. Rest = R9.
// ----------------------------------------------------------------------------

#define MAXN 10000
#define MAXE 320000
#define MAXET (MAXE + MAXN)

#define IN_DIM 256
#define H1_DIM 256
#define HEADS 4
#define HID 64
#define OUT_DIM 40

// ------------------------------ scratch ------------------------------------
__device__ __align__(16) float g_h1[MAXN * H1_DIM];
__device__ __align__(16) float g_out1[MAXN * H1_DIM];
__device__ __align__(16) float g_as1[MAXN * HEADS];
__device__ __align__(16) float g_ad1[MAXN * HEADS];

__device__ __align__(16) float g_h2[MAXN * OUT_DIM];
__device__ float g_as2[MAXN];
__device__ float g_ad2[MAXN];

__device__ int g_deg[MAXN];        // static-zero; re-zeroed by k_scatter each run
__device__ int g_rowptr[MAXN + 1];
__device__ int g_cursor[MAXN];
__device__ int g_csr_src[MAXET];

__device__ __forceinline__ float lrelu(float t) { return t > 0.f ? t : 0.2f * t; }

__device__ __forceinline__ uint32_t f2tf32(float x) {
    uint32_t r;
    asm("cvt.rna.tf32.f32 %0, %1;" : "=r"(r) : "f"(x));
    return r;
}
__device__ __forceinline__ void split_tf32(float x, uint32_t& hi, uint32_t& lo) {
    hi = f2tf32(x);
    lo = f2tf32(x - __uint_as_float(hi));
}

__device__ __forceinline__ void mma_tf32(float c[4], uint32_t a0, uint32_t a1,
                                         uint32_t a2, uint32_t a3,
                                         uint32_t b0, uint32_t b1) {
    asm volatile(
        "mma.sync.aligned.m16n8k8.row.col.f32.tf32.tf32.f32 "
        "{%0,%1,%2,%3}, {%4,%5,%6,%7}, {%8,%9}, {%0,%1,%2,%3};"
        : "+f"(c[0]), "+f"(c[1]), "+f"(c[2]), "+f"(c[3])
        : "r"(a0), "r"(a1), "r"(a2), "r"(a3), "r"(b0), "r"(b1));
}

// ------------------------------ CSR build -----------------------------------
__global__ void k_deg(const int* __restrict__ ei, int E) {
    int e = blockIdx.x * blockDim.x + threadIdx.x;
    if (e < E) atomicAdd(&g_deg[ei[E + e]], 1);
}

__global__ void k_scan(int N) {
    int tid = threadIdx.x;
    const int C = (N + 1023) >> 10;
    int start = tid * C;
    int local[16];
    int sum = 0;
#pragma unroll
    for (int j = 0; j < 16; j++) {
        if (j >= C) break;
        int i = start + j;
        int v = (i < N) ? (g_deg[i] + 1) : 0;   // +1 self loop
        local[j] = sum;
        sum += v;
    }
    int lane = tid & 31, warp = tid >> 5;
    int inc = sum;
#pragma unroll
    for (int off = 1; off < 32; off <<= 1) {
        int t = __shfl_up_sync(0xffffffffu, inc, off);
        if (lane >= off) inc += t;
    }
    __shared__ int wtot[32];
    if (lane == 31) wtot[warp] = inc;
    __syncthreads();
    if (warp == 0) {
        int v = wtot[lane];
#pragma unroll
        for (int off = 1; off < 32; off <<= 1) {
            int t = __shfl_up_sync(0xffffffffu, v, off);
            if (lane >= off) v += t;
        }
        wtot[lane] = v;
    }
    __syncthreads();
    int carry = (warp > 0 ? wtot[warp - 1] : 0) + (inc - sum);
#pragma unroll
    for (int j = 0; j < 16; j++) {
        if (j >= C) break;
        int i = start + j;
        if (i < N) {
            int e = carry + local[j];
            g_rowptr[i] = e;
            g_cursor[i] = e;
        }
    }
    if (tid == 1023) g_rowptr[N] = wtot[31];
}

__global__ void k_scatter(const int* __restrict__ ei, int E, int ET) {
    int e = blockIdx.x * blockDim.x + threadIdx.x;
    if (e >= ET) return;
    int s, d;
    if (e < E) { s = ei[e]; d = ei[E + e]; }
    else       { s = d = e - E; g_deg[d] = 0; }   // reset for next launch
    int pos = atomicAdd(&g_cursor[d], 1);
    g_csr_src[pos] = s;
}

// ---------------- GEMM1 [N,256]x[256,256] tf32 MMA + fused alpha1 -----------
// tile 64x128, BK=16, 8 warps (4 m x 2 n); split-at-store hi/lo smem tiles
#define ASTRIDE 20
#define BSTRIDE 132    // 16B-aligned rows, conflict-free frags

__global__ __launch_bounds__(256, 2)
void k_gemm1(const float* __restrict__ A, const float* __restrict__ B,
             const float* __restrict__ att_s, const float* __restrict__ att_d,
             int M) {
    __shared__ uint32_t As_hi[64][ASTRIDE], As_lo[64][ASTRIDE];
    __shared__ uint32_t Bs_hi[16][BSTRIDE], Bs_lo[16][BSTRIDE];

    int tid = threadIdx.x;
    int lane = tid & 31, warp = tid >> 5;
    int warp_m = warp & 3, warp_n = warp >> 2;
    int groupID = lane >> 2, tid4 = lane & 3;
    int rowBase = blockIdx.y * 64;
    int colBase = blockIdx.x * 128;

    float acc[8][4] = {};

    for (int k0 = 0; k0 < IN_DIM; k0 += 16) {
        // A tile: 64 rows x 16 cols, split at store
        {
            int r = tid >> 2, c4 = tid & 3;
            int gr = rowBase + r;
            float4 v = make_float4(0.f, 0.f, 0.f, 0.f);
            if (gr < M) v = *(const float4*)&A[gr * IN_DIM + k0 + c4 * 4];
            uint4 h, l;
            split_tf32(v.x, h.x, l.x);
            split_tf32(v.y, h.y, l.y);
            split_tf32(v.z, h.z, l.z);
            split_tf32(v.w, h.w, l.w);
            *(uint4*)&As_hi[r][c4 * 4] = h;
            *(uint4*)&As_lo[r][c4 * 4] = l;
        }
        // B tile: 16 rows x 128 cols, split at store
#pragma unroll
        for (int i = 0; i < 2; i++) {
            int f = tid + i * 256;            // 0..511
            int r = f >> 5, c4 = f & 31;
            float4 v = *(const float4*)&B[(k0 + r) * H1_DIM + colBase + c4 * 4];
            uint4 h, l;
            split_tf32(v.x, h.x, l.x);
            split_tf32(v.y, h.y, l.y);
            split_tf32(v.z, h.z, l.z);
            split_tf32(v.w, h.w, l.w);
            *(uint4*)&Bs_hi[r][c4 * 4] = h;
            *(uint4*)&Bs_lo[r][c4 * 4] = l;
        }
        __syncthreads();

#pragma unroll
        for (int kk = 0; kk < 2; kk++) {
            int kc0 = kk * 8;
            uint32_t ah[4], al[4];
            int row = warp_m * 16 + groupID;
            ah[0] = As_hi[row][kc0 + tid4];
            ah[1] = As_hi[row + 8][kc0 + tid4];
            ah[2] = As_hi[row][kc0 + tid4 + 4];
            ah[3] = As_hi[row + 8][kc0 + tid4 + 4];
            al[0] = As_lo[row][kc0 + tid4];
            al[1] = As_lo[row + 8][kc0 + tid4];
            al[2] = As_lo[row][kc0 + tid4 + 4];
            al[3] = As_lo[row + 8][kc0 + tid4 + 4];
#pragma unroll
            for (int nt = 0; nt < 8; nt++) {
                int n = warp_n * 64 + nt * 8 + groupID;
                uint32_t bh0 = Bs_hi[kc0 + tid4][n];
                uint32_t bh1 = Bs_hi[kc0 + tid4 + 4][n];
                uint32_t bl0 = Bs_lo[kc0 + tid4][n];
                uint32_t bl1 = Bs_lo[kc0 + tid4 + 4][n];
                mma_tf32(acc[nt], ah[0], ah[1], ah[2], ah[3], bh0, bh1);
                mma_tf32(acc[nt], al[0], al[1], al[2], al[3], bh0, bh1);
                mma_tf32(acc[nt], ah[0], ah[1], ah[2], ah[3], bl0, bl1);
            }
        }
        __syncthreads();
    }

    // ---- store h1 + fused alpha1 (warp covers one full head) ----
    int head = (colBase >> 6) + warp_n;
    float ss[2] = {0.f, 0.f}, sd[2] = {0.f, 0.f};   // [half]
    int row0 = rowBase + warp_m * 16 + groupID;
    int row1 = row0 + 8;
#pragma unroll
    for (int nt = 0; nt < 8; nt++) {
        int col = colBase + warp_n * 64 + nt * 8 + tid4 * 2;
        float a_s0 = att_s[col], a_s1 = att_s[col + 1];
        float a_d0 = att_d[col], a_d1 = att_d[col + 1];
        float c0 = acc[nt][0], c1 = acc[nt][1];
        float c2 = acc[nt][2], c3 = acc[nt][3];
        if (row0 < M) *(float2*)&g_h1[row0 * H1_DIM + col] = make_float2(c0, c1);
        if (row1 < M) *(float2*)&g_h1[row1 * H1_DIM + col] = make_float2(c2, c3);
        ss[0] = fmaf(c0, a_s0, fmaf(c1, a_s1, ss[0]));
        ss[1] = fmaf(c2, a_s0, fmaf(c3, a_s1, ss[1]));
        sd[0] = fmaf(c0, a_d0, fmaf(c1, a_d1, sd[0]));
        sd[1] = fmaf(c2, a_d0, fmaf(c3, a_d1, sd[1]));
    }
#pragma unroll
    for (int hf = 0; hf < 2; hf++) {
#pragma unroll
        for (int off = 1; off < 4; off <<= 1) {
            ss[hf] += __shfl_xor_sync(0xffffffffu, ss[hf], off);
            sd[hf] += __shfl_xor_sync(0xffffffffu, sd[hf], off);
        }
        if (tid4 == 0) {
            int row = rowBase + warp_m * 16 + groupID + hf * 8;
            if (row < M) {
                g_as1[row * HEADS + head] = ss[hf];
                g_ad1[row * HEADS + head] = sd[hf];
            }
        }
    }
}

// ---- fused L1 single-pass softmax + aggregate + bias + relu (block/dst) ----
__global__ void k_agg1(const float* __restrict__ bias) {
    int n = blockIdx.x;
    int tid = threadIdx.x;
    int beg = g_rowptr[n];
    int deg = g_rowptr[n + 1] - beg;
    int lane = tid & 31, warp = tid >> 5;

    __shared__ int    sh_src[64];
    __shared__ float  sh_w[HEADS][64];
    __shared__ float4 sh_s[8];
    __shared__ float  sh_inv[HEADS];
    __shared__ float  sh_red[4][H1_DIM];

    float4 ad4 = *(const float4*)&g_ad1[n * HEADS];

    int g = tid >> 6, c4 = tid & 63, head = c4 >> 4;
    float4 acc = make_float4(0.f, 0.f, 0.f, 0.f);
    float4 sacc = make_float4(0.f, 0.f, 0.f, 0.f);

    for (int base = 0; base < deg; base += 64) {
        int len = min(64, deg - base);
        __syncthreads();
        if (tid < len) {
            int src = g_csr_src[beg + base + tid];
            sh_src[tid] = src;
            float4 as = *(const float4*)&g_as1[src * HEADS];
            float e0 = __expf(lrelu(as.x + ad4.x));
            float e1 = __expf(lrelu(as.y + ad4.y));
            float e2 = __expf(lrelu(as.z + ad4.z));
            float e3 = __expf(lrelu(as.w + ad4.w));
            sh_w[0][tid] = e0; sh_w[1][tid] = e1;
            sh_w[2][tid] = e2; sh_w[3][tid] = e3;
            sacc.x += e0; sacc.y += e1; sacc.z += e2; sacc.w += e3;
        }
        __syncthreads();
        for (int k = g; k < len; k += 4) {
            float w = sh_w[head][k];
            float4 v = *(const float4*)&g_h1[sh_src[k] * H1_DIM + c4 * 4];
            acc.x = fmaf(w, v.x, acc.x);
            acc.y = fmaf(w, v.y, acc.y);
            acc.z = fmaf(w, v.z, acc.z);
            acc.w = fmaf(w, v.w, acc.w);
        }
    }
#pragma unroll
    for (int off = 16; off > 0; off >>= 1) {
        sacc.x += __shfl_xor_sync(0xffffffffu, sacc.x, off);
        sacc.y += __shfl_xor_sync(0xffffffffu, sacc.y, off);
        sacc.z += __shfl_xor_sync(0xffffffffu, sacc.z, off);
        sacc.w += __shfl_xor_sync(0xffffffffu, sacc.w, off);
    }
    if (lane == 0) sh_s[warp] = sacc;
    __syncthreads();
    if (tid == 0) {
        float4 s = sh_s[0];
#pragma unroll
        for (int w = 1; w < 8; w++) {
            s.x += sh_s[w].x; s.y += sh_s[w].y;
            s.z += sh_s[w].z; s.w += sh_s[w].w;
        }
        sh_inv[0] = 1.f / s.x; sh_inv[1] = 1.f / s.y;
        sh_inv[2] = 1.f / s.z; sh_inv[3] = 1.f / s.w;
    }
    *(float4*)&sh_red[g][c4 * 4] = acc;
    __syncthreads();
    int c = tid;
    float v = (sh_red[0][c] + sh_red[1][c] + sh_red[2][c] + sh_red[3][c])
              * sh_inv[c >> 6] + bias[c];
    g_out1[n * H1_DIM + c] = v > 0.f ? v : 0.f;
}

// ---------------- GEMM2 [N,256]x[256,40] + fused alpha2 ---------------------
__global__ void k_gemm2(const float* __restrict__ W2,
                        const float* __restrict__ att_s,
                        const float* __restrict__ att_d, int M) {
    __shared__ float W2s[64 * OUT_DIM];
    __shared__ float hr[32 * 64];
    __shared__ float sh_o[32 * OUT_DIM];
    int tid = threadIdx.x;
    int rowBase = blockIdx.x * 32;
    float acc[5] = {0.f, 0.f, 0.f, 0.f, 0.f};
    for (int k0 = 0; k0 < H1_DIM; k0 += 64) {
        for (int idx = tid; idx < 64 * OUT_DIM; idx += 256)
            W2s[idx] = W2[(k0 + idx / OUT_DIM) * OUT_DIM + idx % OUT_DIM];
        for (int f = tid; f < 512; f += 256) {
            int r = f >> 4, c4 = f & 15;
            int row = rowBase + r;
            float4 v = make_float4(0.f, 0.f, 0.f, 0.f);
            if (row < M) v = *(const float4*)&g_out1[row * H1_DIM + k0 + c4 * 4];
            *(float4*)&hr[r * 64 + c4 * 4] = v;
        }
        __syncthreads();
#pragma unroll
        for (int oi = 0; oi < 5; oi++) {
            int out_idx = tid + oi * 256;
            int r = out_idx / OUT_DIM, c = out_idx % OUT_DIM;
            float a = acc[oi];
#pragma unroll 8
            for (int k = 0; k < 64; k++)
                a = fmaf(hr[r * 64 + k], W2s[k * OUT_DIM + c], a);
            acc[oi] = a;
        }
        __syncthreads();
    }
#pragma unroll
    for (int oi = 0; oi < 5; oi++) {
        int out_idx = tid + oi * 256;
        int r = out_idx / OUT_DIM, c = out_idx % OUT_DIM;
        int row = rowBase + r;
        sh_o[out_idx] = acc[oi];
        if (row < M) g_h2[row * OUT_DIM + c] = acc[oi];
    }
    __syncthreads();
    if (tid < 32) {
        int row = rowBase + tid;
        if (row < M) {
            float ss = 0.f, sd = 0.f;
#pragma unroll
            for (int k = 0; k < OUT_DIM; k++) {
                float v = sh_o[tid * OUT_DIM + k];
                ss = fmaf(v, att_s[k], ss);
                sd = fmaf(v, att_d[k], sd);
            }
            g_as2[row] = ss;
            g_ad2[row] = sd;
        }
    }
}

// ---- fused L2 single-pass softmax + aggregate + bias + log_softmax ---------
__global__ void k_agg2(const float* __restrict__ bias, float* __restrict__ out) {
    int n = blockIdx.x;
    int tid = threadIdx.x;
    int beg = g_rowptr[n];
    int deg = g_rowptr[n + 1] - beg;
    int lane = tid & 31, warp = tid >> 5;

    __shared__ int   sh_src[64];
    __shared__ float sh_w[64];
    __shared__ float sh_s[4];
    __shared__ float sh_inv;
    __shared__ float sh_part[128];
    __shared__ float sh_row[OUT_DIM];
    __shared__ float sh_lse;

    float adn = g_ad2[n];

    int eo = tid >> 6, c = tid & 63;
    float acc = 0.f, sacc = 0.f;
    for (int base = 0; base < deg; base += 64) {
        int len = min(64, deg - base);
        __syncthreads();
        if (tid < len) {
            int src = g_csr_src[beg + base + tid];
            sh_src[tid] = src;
            float e = __expf(lrelu(g_as2[src] + adn));
            sh_w[tid] = e;
            sacc += e;
        }
        __syncthreads();
        if (c < OUT_DIM) {
            for (int k = eo; k < len; k += 2)
                acc = fmaf(sh_w[k], g_h2[sh_src[k] * OUT_DIM + c], acc);
        }
    }
#pragma unroll
    for (int off = 16; off > 0; off >>= 1)
        sacc += __shfl_xor_sync(0xffffffffu, sacc, off);
    if (lane == 0) sh_s[warp] = sacc;
    sh_part[tid] = acc;
    __syncthreads();
    if (tid == 0) sh_inv = 1.f / (sh_s[0] + sh_s[1] + sh_s[2] + sh_s[3]);
    __syncthreads();
    if (tid < OUT_DIM)
        sh_row[tid] = (sh_part[tid] + sh_part[tid + 64]) * sh_inv + bias[tid];
    __syncthreads();
    if (tid == 0) {
        float m = -1e30f;
#pragma unroll
        for (int k = 0; k < OUT_DIM; k++) m = fmaxf(m, sh_row[k]);
        float s = 0.f;
#pragma unroll
        for (int k = 0; k < OUT_DIM; k++) s += __expf(sh_row[k] - m);
        sh_lse = m + logf(s);
    }
    __syncthreads();
    if (tid < OUT_DIM) out[n * OUT_DIM + tid] = sh_row[tid] - sh_lse;
}

// ----------------------------------------------------------------------------
extern "C" void kernel_launch(void* const* d_in, const int* in_sizes, int n_in,
                              void* d_out, int out_size) {
    const float* x   = (const float*)d_in[0];
    const int*   ei  = (const int*)d_in[1];
    const float* W1  = (const float*)d_in[2];
    const float* as1 = (const float*)d_in[3];
    const float* ad1 = (const float*)d_in[4];
    const float* b1  = (const float*)d_in[5];
    const float* W2  = (const float*)d_in[6];
    const float* as2 = (const float*)d_in[7];
    const float* ad2 = (const float*)d_in[8];
    const float* b2  = (const float*)d_in[9];
    float* out = (float*)d_out;

    int N  = in_sizes[0] / IN_DIM;
    int E  = in_sizes[1] / 2;
    int ET = E + N;

    // CSR build
    k_deg<<<(E + 255) / 256, 256>>>(ei, E);
    k_scan<<<1, 1024>>>(N);
    k_scatter<<<(ET + 255) / 256, 256>>>(ei, E, ET);

    // layer 1
    {
        dim3 grid(H1_DIM / 128, (N + 63) / 64);
        k_gemm1<<<grid, 256>>>(x, W1, as1, ad1, N);
    }
    k_agg1<<<N, 256>>>(b1);

    // layer 2
    k_gemm2<<<(N + 31) / 32, 256>>>(W2, as2, ad2, N);
    k_agg2<<<N, 128>>>(b2, out);
}

// round 11
// speedup vs baseline: 1.0372x; 1.0372x over previous
#include <cuda_runtime.h>
#include <cuda_bf16.h>
#include <math.h>
#include <stdint.h>

// ----------------------------------------------------------------------------
// SimpleGAT R11: GEMM1 with cp.async double-buffered tile pipeline (hides
// global-load latency that bound R6-R10). Tile 64x128, BK=16, 8 warps,
// in-fragment 3xTF32 split. Rest identical to R9/R10.
// ----------------------------------------------------------------------------

#define MAXN 10000
#define MAXE 320000
#define MAXET (MAXE + MAXN)

#define IN_DIM 256
#define H1_DIM 256
#define HEADS 4
#define HID 64
#define OUT_DIM 40

// ------------------------------ scratch ------------------------------------
__device__ __align__(16) float g_h1[MAXN * H1_DIM];
__device__ __align__(16) float g_out1[MAXN * H1_DIM];
__device__ __align__(16) float g_as1[MAXN * HEADS];
__device__ __align__(16) float g_ad1[MAXN * HEADS];

__device__ __align__(16) float g_h2[MAXN * OUT_DIM];
__device__ float g_as2[MAXN];
__device__ float g_ad2[MAXN];

__device__ int g_deg[MAXN];        // static-zero; re-zeroed by k_scatter each run
__device__ int g_rowptr[MAXN + 1];
__device__ int g_cursor[MAXN];
__device__ int g_csr_src[MAXET];

__device__ __forceinline__ float lrelu(float t) { return t > 0.f ? t : 0.2f * t; }

__device__ __forceinline__ uint32_t f2tf32(float x) {
    uint32_t r;
    asm("cvt.rna.tf32.f32 %0, %1;" : "=r"(r) : "f"(x));
    return r;
}
__device__ __forceinline__ void split_tf32(float x, uint32_t& hi, uint32_t& lo) {
    hi = f2tf32(x);
    lo = f2tf32(x - __uint_as_float(hi));
}

__device__ __forceinline__ void mma_tf32(float c[4], uint32_t a0, uint32_t a1,
                                         uint32_t a2, uint32_t a3,
                                         uint32_t b0, uint32_t b1) {
    asm volatile(
        "mma.sync.aligned.m16n8k8.row.col.f32.tf32.tf32.f32 "
        "{%0,%1,%2,%3}, {%4,%5,%6,%7}, {%8,%9}, {%0,%1,%2,%3};"
        : "+f"(c[0]), "+f"(c[1]), "+f"(c[2]), "+f"(c[3])
        : "r"(a0), "r"(a1), "r"(a2), "r"(a3), "r"(b0), "r"(b1));
}

__device__ __forceinline__ uint32_t smem_u32(const void* p) {
    uint32_t a;
    asm("{ .reg .u64 t; cvta.to.shared.u64 t, %1; cvt.u32.u64 %0, t; }"
        : "=r"(a) : "l"(p));
    return a;
}
__device__ __forceinline__ void cp_async16(uint32_t saddr, const void* gptr,
                                           bool valid) {
    int sz = valid ? 16 : 0;
    asm volatile("cp.async.cg.shared.global [%0], [%1], 16, %2;"
                 :: "r"(saddr), "l"(gptr), "r"(sz));
}

// ------------------------------ CSR build -----------------------------------
__global__ void k_deg(const int* __restrict__ ei, int E) {
    int e = blockIdx.x * blockDim.x + threadIdx.x;
    if (e < E) atomicAdd(&g_deg[ei[E + e]], 1);
}

__global__ void k_scan(int N) {
    int tid = threadIdx.x;
    const int C = (N + 1023) >> 10;
    int start = tid * C;
    int local[16];
    int sum = 0;
#pragma unroll
    for (int j = 0; j < 16; j++) {
        if (j >= C) break;
        int i = start + j;
        int v = (i < N) ? (g_deg[i] + 1) : 0;   // +1 self loop
        local[j] = sum;
        sum += v;
    }
    int lane = tid & 31, warp = tid >> 5;
    int inc = sum;
#pragma unroll
    for (int off = 1; off < 32; off <<= 1) {
        int t = __shfl_up_sync(0xffffffffu, inc, off);
        if (lane >= off) inc += t;
    }
    __shared__ int wtot[32];
    if (lane == 31) wtot[warp] = inc;
    __syncthreads();
    if (warp == 0) {
        int v = wtot[lane];
#pragma unroll
        for (int off = 1; off < 32; off <<= 1) {
            int t = __shfl_up_sync(0xffffffffu, v, off);
            if (lane >= off) v += t;
        }
        wtot[lane] = v;
    }
    __syncthreads();
    int carry = (warp > 0 ? wtot[warp - 1] : 0) + (inc - sum);
#pragma unroll
    for (int j = 0; j < 16; j++) {
        if (j >= C) break;
        int i = start + j;
        if (i < N) {
            int e = carry + local[j];
            g_rowptr[i] = e;
            g_cursor[i] = e;
        }
    }
    if (tid == 1023) g_rowptr[N] = wtot[31];
}

__global__ void k_scatter(const int* __restrict__ ei, int E, int ET) {
    int e = blockIdx.x * blockDim.x + threadIdx.x;
    if (e >= ET) return;
    int s, d;
    if (e < E) { s = ei[e]; d = ei[E + e]; }
    else       { s = d = e - E; g_deg[d] = 0; }   // reset for next launch
    int pos = atomicAdd(&g_cursor[d], 1);
    g_csr_src[pos] = s;
}

// ---------------- GEMM1 [N,256]x[256,256] tf32 MMA + fused alpha1 -----------
// tile 64x128, BK=16, 8 warps (4m x 2n); cp.async double-buffered pipeline
#define ASTRIDE 20
#define BSTRIDE 132
#define NSTAGE  (IN_DIM / 16)   // 16

__global__ __launch_bounds__(256, 2)
void k_gemm1(const float* __restrict__ A, const float* __restrict__ B,
             const float* __restrict__ att_s, const float* __restrict__ att_d,
             int M) {
    __shared__ float As[2][64][ASTRIDE];
    __shared__ float Bs[2][16][BSTRIDE];

    int tid = threadIdx.x;
    int lane = tid & 31, warp = tid >> 5;
    int warp_m = warp & 3, warp_n = warp >> 2;
    int groupID = lane >> 2, tid4 = lane & 3;
    int rowBase = blockIdx.y * 64;
    int colBase = blockIdx.x * 128;

    // per-thread load coordinates
    int a_r = tid >> 2, a_c4 = tid & 3;
    int a_row = rowBase + a_r;
    bool a_ok = a_row < M;
    const float* a_base = &A[(a_ok ? a_row : 0) * IN_DIM + a_c4 * 4];
    int b_r0 = tid >> 5, b_c40 = tid & 31;           // i=0
    int b_r1 = (tid + 256) >> 5, b_c41 = tid & 31;   // i=1

    float acc[8][4] = {};

    // ---- prologue: stage 0 ----
    cp_async16(smem_u32(&As[0][a_r][a_c4 * 4]), a_base, a_ok);
    cp_async16(smem_u32(&Bs[0][b_r0][b_c40 * 4]),
               &B[b_r0 * H1_DIM + colBase + b_c40 * 4], true);
    cp_async16(smem_u32(&Bs[0][b_r1][b_c41 * 4]),
               &B[b_r1 * H1_DIM + colBase + b_c41 * 4], true);
    asm volatile("cp.async.commit_group;");

    for (int s = 0; s < NSTAGE; s++) {
        int cur = s & 1;
        if (s + 1 < NSTAGE) {
            int nxt = cur ^ 1, k0 = (s + 1) * 16;
            cp_async16(smem_u32(&As[nxt][a_r][a_c4 * 4]), a_base + k0, a_ok);
            cp_async16(smem_u32(&Bs[nxt][b_r0][b_c40 * 4]),
                       &B[(k0 + b_r0) * H1_DIM + colBase + b_c40 * 4], true);
            cp_async16(smem_u32(&Bs[nxt][b_r1][b_c41 * 4]),
                       &B[(k0 + b_r1) * H1_DIM + colBase + b_c41 * 4], true);
            asm volatile("cp.async.commit_group;");
            asm volatile("cp.async.wait_group 1;");
        } else {
            asm volatile("cp.async.wait_group 0;");
        }
        __syncthreads();

#pragma unroll
        for (int kk = 0; kk < 2; kk++) {
            int kc0 = kk * 8;
            uint32_t ah[4], al[4];
            int row = warp_m * 16 + groupID;
            split_tf32(As[cur][row][kc0 + tid4],         ah[0], al[0]);
            split_tf32(As[cur][row + 8][kc0 + tid4],     ah[1], al[1]);
            split_tf32(As[cur][row][kc0 + tid4 + 4],     ah[2], al[2]);
            split_tf32(As[cur][row + 8][kc0 + tid4 + 4], ah[3], al[3]);
#pragma unroll
            for (int nt = 0; nt < 8; nt++) {
                int n = warp_n * 64 + nt * 8 + groupID;
                uint32_t bh0, bl0, bh1, bl1;
                split_tf32(Bs[cur][kc0 + tid4][n],     bh0, bl0);
                split_tf32(Bs[cur][kc0 + tid4 + 4][n], bh1, bl1);
                mma_tf32(acc[nt], ah[0], ah[1], ah[2], ah[3], bh0, bh1);
                mma_tf32(acc[nt], al[0], al[1], al[2], al[3], bh0, bh1);
                mma_tf32(acc[nt], ah[0], ah[1], ah[2], ah[3], bl0, bl1);
            }
        }
        __syncthreads();
    }

    // ---- store h1 + fused alpha1 (warp covers one full head) ----
    int head = (colBase >> 6) + warp_n;
    float ss[2] = {0.f, 0.f}, sd[2] = {0.f, 0.f};
    int row0 = rowBase + warp_m * 16 + groupID;
    int row1 = row0 + 8;
#pragma unroll
    for (int nt = 0; nt < 8; nt++) {
        int col = colBase + warp_n * 64 + nt * 8 + tid4 * 2;
        float a_s0 = att_s[col], a_s1 = att_s[col + 1];
        float a_d0 = att_d[col], a_d1 = att_d[col + 1];
        float c0 = acc[nt][0], c1 = acc[nt][1];
        float c2 = acc[nt][2], c3 = acc[nt][3];
        if (row0 < M) *(float2*)&g_h1[row0 * H1_DIM + col] = make_float2(c0, c1);
        if (row1 < M) *(float2*)&g_h1[row1 * H1_DIM + col] = make_float2(c2, c3);
        ss[0] = fmaf(c0, a_s0, fmaf(c1, a_s1, ss[0]));
        ss[1] = fmaf(c2, a_s0, fmaf(c3, a_s1, ss[1]));
        sd[0] = fmaf(c0, a_d0, fmaf(c1, a_d1, sd[0]));
        sd[1] = fmaf(c2, a_d0, fmaf(c3, a_d1, sd[1]));
    }
#pragma unroll
    for (int hf = 0; hf < 2; hf++) {
#pragma unroll
        for (int off = 1; off < 4; off <<= 1) {
            ss[hf] += __shfl_xor_sync(0xffffffffu, ss[hf], off);
            sd[hf] += __shfl_xor_sync(0xffffffffu, sd[hf], off);
        }
        if (tid4 == 0) {
            int row = rowBase + warp_m * 16 + groupID + hf * 8;
            if (row < M) {
                g_as1[row * HEADS + head] = ss[hf];
                g_ad1[row * HEADS + head] = sd[hf];
            }
        }
    }
}

// ---- fused L1 single-pass softmax + aggregate + bias + relu (block/dst) ----
__global__ void k_agg1(const float* __restrict__ bias) {
    int n = blockIdx.x;
    int tid = threadIdx.x;
    int beg = g_rowptr[n];
    int deg = g_rowptr[n + 1] - beg;
    int lane = tid & 31, warp = tid >> 5;

    __shared__ int    sh_src[64];
    __shared__ float  sh_w[HEADS][64];
    __shared__ float4 sh_s[8];
    __shared__ float  sh_inv[HEADS];
    __shared__ float  sh_red[4][H1_DIM];

    float4 ad4 = *(const float4*)&g_ad1[n * HEADS];

    int g = tid >> 6, c4 = tid & 63, head = c4 >> 4;
    float4 acc = make_float4(0.f, 0.f, 0.f, 0.f);
    float4 sacc = make_float4(0.f, 0.f, 0.f, 0.f);

    for (int base = 0; base < deg; base += 64) {
        int len = min(64, deg - base);
        __syncthreads();
        if (tid < len) {
            int src = g_csr_src[beg + base + tid];
            sh_src[tid] = src;
            float4 as = *(const float4*)&g_as1[src * HEADS];
            float e0 = __expf(lrelu(as.x + ad4.x));
            float e1 = __expf(lrelu(as.y + ad4.y));
            float e2 = __expf(lrelu(as.z + ad4.z));
            float e3 = __expf(lrelu(as.w + ad4.w));
            sh_w[0][tid] = e0; sh_w[1][tid] = e1;
            sh_w[2][tid] = e2; sh_w[3][tid] = e3;
            sacc.x += e0; sacc.y += e1; sacc.z += e2; sacc.w += e3;
        }
        __syncthreads();
        for (int k = g; k < len; k += 4) {
            float w = sh_w[head][k];
            float4 v = *(const float4*)&g_h1[sh_src[k] * H1_DIM + c4 * 4];
            acc.x = fmaf(w, v.x, acc.x);
            acc.y = fmaf(w, v.y, acc.y);
            acc.z = fmaf(w, v.z, acc.z);
            acc.w = fmaf(w, v.w, acc.w);
        }
    }
#pragma unroll
    for (int off = 16; off > 0; off >>= 1) {
        sacc.x += __shfl_xor_sync(0xffffffffu, sacc.x, off);
        sacc.y += __shfl_xor_sync(0xffffffffu, sacc.y, off);
        sacc.z += __shfl_xor_sync(0xffffffffu, sacc.z, off);
        sacc.w += __shfl_xor_sync(0xffffffffu, sacc.w, off);
    }
    if (lane == 0) sh_s[warp] = sacc;
    __syncthreads();
    if (tid == 0) {
        float4 s = sh_s[0];
#pragma unroll
        for (int w = 1; w < 8; w++) {
            s.x += sh_s[w].x; s.y += sh_s[w].y;
            s.z += sh_s[w].z; s.w += sh_s[w].w;
        }
        sh_inv[0] = 1.f / s.x; sh_inv[1] = 1.f / s.y;
        sh_inv[2] = 1.f / s.z; sh_inv[3] = 1.f / s.w;
    }
    *(float4*)&sh_red[g][c4 * 4] = acc;
    __syncthreads();
    int c = tid;
    float v = (sh_red[0][c] + sh_red[1][c] + sh_red[2][c] + sh_red[3][c])
              * sh_inv[c >> 6] + bias[c];
    g_out1[n * H1_DIM + c] = v > 0.f ? v : 0.f;
}

// ---------------- GEMM2 [N,256]x[256,40] + fused alpha2 ---------------------
__global__ void k_gemm2(const float* __restrict__ W2,
                        const float* __restrict__ att_s,
                        const float* __restrict__ att_d, int M) {
    __shared__ float W2s[64 * OUT_DIM];
    __shared__ float hr[32 * 64];
    __shared__ float sh_o[32 * OUT_DIM];
    int tid = threadIdx.x;
    int rowBase = blockIdx.x * 32;
    float acc[5] = {0.f, 0.f, 0.f, 0.f, 0.f};
    for (int k0 = 0; k0 < H1_DIM; k0 += 64) {
        for (int idx = tid; idx < 64 * OUT_DIM; idx += 256)
            W2s[idx] = W2[(k0 + idx / OUT_DIM) * OUT_DIM + idx % OUT_DIM];
        for (int f = tid; f < 512; f += 256) {
            int r = f >> 4, c4 = f & 15;
            int row = rowBase + r;
            float4 v = make_float4(0.f, 0.f, 0.f, 0.f);
            if (row < M) v = *(const float4*)&g_out1[row * H1_DIM + k0 + c4 * 4];
            *(float4*)&hr[r * 64 + c4 * 4] = v;
        }
        __syncthreads();
#pragma unroll
        for (int oi = 0; oi < 5; oi++) {
            int out_idx = tid + oi * 256;
            int r = out_idx / OUT_DIM, c = out_idx % OUT_DIM;
            float a = acc[oi];
#pragma unroll 8
            for (int k = 0; k < 64; k++)
                a = fmaf(hr[r * 64 + k], W2s[k * OUT_DIM + c], a);
            acc[oi] = a;
        }
        __syncthreads();
    }
#pragma unroll
    for (int oi = 0; oi < 5; oi++) {
        int out_idx = tid + oi * 256;
        int r = out_idx / OUT_DIM, c = out_idx % OUT_DIM;
        int row = rowBase + r;
        sh_o[out_idx] = acc[oi];
        if (row < M) g_h2[row * OUT_DIM + c] = acc[oi];
    }
    __syncthreads();
    if (tid < 32) {
        int row = rowBase + tid;
        if (row < M) {
            float ss = 0.f, sd = 0.f;
#pragma unroll
            for (int k = 0; k < OUT_DIM; k++) {
                float v = sh_o[tid * OUT_DIM + k];
                ss = fmaf(v, att_s[k], ss);
                sd = fmaf(v, att_d[k], sd);
            }
            g_as2[row] = ss;
            g_ad2[row] = sd;
        }
    }
}

// ---- fused L2 single-pass softmax + aggregate + bias + log_softmax ---------
__global__ void k_agg2(const float* __restrict__ bias, float* __restrict__ out) {
    int n = blockIdx.x;
    int tid = threadIdx.x;
    int beg = g_rowptr[n];
    int deg = g_rowptr[n + 1] - beg;
    int lane = tid & 31, warp = tid >> 5;

    __shared__ int   sh_src[64];
    __shared__ float sh_w[64];
    __shared__ float sh_s[4];
    __shared__ float sh_inv;
    __shared__ float sh_part[128];
    __shared__ float sh_row[OUT_DIM];
    __shared__ float sh_lse;

    float adn = g_ad2[n];

    int eo = tid >> 6, c = tid & 63;
    float acc = 0.f, sacc = 0.f;
    for (int base = 0; base < deg; base += 64) {
        int len = min(64, deg - base);
        __syncthreads();
        if (tid < len) {
            int src = g_csr_src[beg + base + tid];
            sh_src[tid] = src;
            float e = __expf(lrelu(g_as2[src] + adn));
            sh_w[tid] = e;
            sacc += e;
        }
        __syncthreads();
        if (c < OUT_DIM) {
            for (int k = eo; k < len; k += 2)
                acc = fmaf(sh_w[k], g_h2[sh_src[k] * OUT_DIM + c], acc);
        }
    }
#pragma unroll
    for (int off = 16; off > 0; off >>= 1)
        sacc += __shfl_xor_sync(0xffffffffu, sacc, off);
    if (lane == 0) sh_s[warp] = sacc;
    sh_part[tid] = acc;
    __syncthreads();
    if (tid == 0) sh_inv = 1.f / (sh_s[0] + sh_s[1] + sh_s[2] + sh_s[3]);
    __syncthreads();
    if (tid < OUT_DIM)
        sh_row[tid] = (sh_part[tid] + sh_part[tid + 64]) * sh_inv + bias[tid];
    __syncthreads();
    if (tid == 0) {
        float m = -1e30f;
#pragma unroll
        for (int k = 0; k < OUT_DIM; k++) m = fmaxf(m, sh_row[k]);
        float s = 0.f;
#pragma unroll
        for (int k = 0; k < OUT_DIM; k++) s += __expf(sh_row[k] - m);
        sh_lse = m + logf(s);
    }
    __syncthreads();
    if (tid < OUT_DIM) out[n * OUT_DIM + tid] = sh_row[tid] - sh_lse;
}

// ----------------------------------------------------------------------------
extern "C" void kernel_launch(void* const* d_in, const int* in_sizes, int n_in,
                              void* d_out, int out_size) {
    const float* x   = (const float*)d_in[0];
    const int*   ei  = (const int*)d_in[1];
    const float* W1  = (const float*)d_in[2];
    const float* as1 = (const float*)d_in[3];
    const float* ad1 = (const float*)d_in[4];
    const float* b1  = (const float*)d_in[5];
    const float* W2  = (const float*)d_in[6];
    const float* as2 = (const float*)d_in[7];
    const float* ad2 = (const float*)d_in[8];
    const float* b2  = (const float*)d_in[9];
    float* out = (float*)d_out;

    int N  = in_sizes[0] / IN_DIM;
    int E  = in_sizes[1] / 2;
    int ET = E + N;

    // CSR build
    k_deg<<<(E + 255) / 256, 256>>>(ei, E);
    k_scan<<<1, 1024>>>(N);
    k_scatter<<<(ET + 255) / 256, 256>>>(ei, E, ET);

    // layer 1
    {
        dim3 grid(H1_DIM / 128, (N + 63) / 64);
        k_gemm1<<<grid, 256>>>(x, W1, as1, ad1, N);
    }
    k_agg1<<<N, 256>>>(b1);

    // layer 2
    k_gemm2<<<(N + 31) / 32, 256>>>(W2, as2, ad2, N);
    k_agg2<<<N, 128>>>(b2, out);
}

// round 12
// speedup vs baseline: 1.1687x; 1.1268x over previous
#include <cuda_runtime.h>
#include <cuda_bf16.h>
#include <math.h>
#include <stdint.h>

// ----------------------------------------------------------------------------
// SimpleGAT R12: GEMM1 with bf16x3 compensated tensor-core MMA (m16n8k16),
// packed hi/lo bf16x2 smem tiles, register-staged double buffering.
// Rest identical to R11.
// ----------------------------------------------------------------------------

#define MAXN 10000
#define MAXE 320000
#define MAXET (MAXE + MAXN)

#define IN_DIM 256
#define H1_DIM 256
#define HEADS 4
#define HID 64
#define OUT_DIM 40

// ------------------------------ scratch ------------------------------------
__device__ __align__(16) float g_h1[MAXN * H1_DIM];
__device__ __align__(16) float g_out1[MAXN * H1_DIM];
__device__ __align__(16) float g_as1[MAXN * HEADS];
__device__ __align__(16) float g_ad1[MAXN * HEADS];

__device__ __align__(16) float g_h2[MAXN * OUT_DIM];
__device__ float g_as2[MAXN];
__device__ float g_ad2[MAXN];

__device__ int g_deg[MAXN];        // static-zero; re-zeroed by k_scatter each run
__device__ int g_rowptr[MAXN + 1];
__device__ int g_cursor[MAXN];
__device__ int g_csr_src[MAXET];

__device__ __forceinline__ float lrelu(float t) { return t > 0.f ? t : 0.2f * t; }

// pack truncated-bf16 his of (x=k_even, y=k_odd): lower half = x_hi
__device__ __forceinline__ uint32_t pack_hi(uint32_t ux, uint32_t uy) {
    uint32_t d;
    asm("prmt.b32 %0, %1, %2, 0x7632;" : "=r"(d) : "r"(ux), "r"(uy));
    return d;
}
// pack bf16(lo) pair: lower half = le (k even), upper = lo (k odd)
__device__ __forceinline__ uint32_t pack_lo(float le, float lo) {
    uint32_t d;
    asm("cvt.rn.bf16x2.f32 %0, %1, %2;" : "=r"(d) : "f"(lo), "f"(le));
    return d;
}
// split a float pair (x even-k, y odd-k) into packed hi/lo bf16x2 words
__device__ __forceinline__ void split_pair(float x, float y,
                                           uint32_t& hi, uint32_t& lo) {
    uint32_t ux = __float_as_uint(x), uy = __float_as_uint(y);
    hi = pack_hi(ux, uy);
    float xr = x - __uint_as_float(ux & 0xFFFF0000u);
    float yr = y - __uint_as_float(uy & 0xFFFF0000u);
    lo = pack_lo(xr, yr);
}

__device__ __forceinline__ void mma_bf16(float c[4], uint32_t a0, uint32_t a1,
                                         uint32_t a2, uint32_t a3,
                                         uint32_t b0, uint32_t b1) {
    asm volatile(
        "mma.sync.aligned.m16n8k16.row.col.f32.bf16.bf16.f32 "
        "{%0,%1,%2,%3}, {%4,%5,%6,%7}, {%8,%9}, {%0,%1,%2,%3};"
        : "+f"(c[0]), "+f"(c[1]), "+f"(c[2]), "+f"(c[3])
        : "r"(a0), "r"(a1), "r"(a2), "r"(a3), "r"(b0), "r"(b1));
}

// ------------------------------ CSR build -----------------------------------
__global__ void k_deg(const int* __restrict__ ei, int E) {
    int e = blockIdx.x * blockDim.x + threadIdx.x;
    if (e < E) atomicAdd(&g_deg[ei[E + e]], 1);
}

__global__ void k_scan(int N) {
    int tid = threadIdx.x;
    const int C = (N + 1023) >> 10;
    int start = tid * C;
    int local[16];
    int sum = 0;
#pragma unroll
    for (int j = 0; j < 16; j++) {
        if (j >= C) break;
        int i = start + j;
        int v = (i < N) ? (g_deg[i] + 1) : 0;   // +1 self loop
        local[j] = sum;
        sum += v;
    }
    int lane = tid & 31, warp = tid >> 5;
    int inc = sum;
#pragma unroll
    for (int off = 1; off < 32; off <<= 1) {
        int t = __shfl_up_sync(0xffffffffu, inc, off);
        if (lane >= off) inc += t;
    }
    __shared__ int wtot[32];
    if (lane == 31) wtot[warp] = inc;
    __syncthreads();
    if (warp == 0) {
        int v = wtot[lane];
#pragma unroll
        for (int off = 1; off < 32; off <<= 1) {
            int t = __shfl_up_sync(0xffffffffu, v, off);
            if (lane >= off) v += t;
        }
        wtot[lane] = v;
    }
    __syncthreads();
    int carry = (warp > 0 ? wtot[warp - 1] : 0) + (inc - sum);
#pragma unroll
    for (int j = 0; j < 16; j++) {
        if (j >= C) break;
        int i = start + j;
        if (i < N) {
            int e = carry + local[j];
            g_rowptr[i] = e;
            g_cursor[i] = e;
        }
    }
    if (tid == 1023) g_rowptr[N] = wtot[31];
}

__global__ void k_scatter(const int* __restrict__ ei, int E, int ET) {
    int e = blockIdx.x * blockDim.x + threadIdx.x;
    if (e >= ET) return;
    int s, d;
    if (e < E) { s = ei[e]; d = ei[E + e]; }
    else       { s = d = e - E; g_deg[d] = 0; }   // reset for next launch
    int pos = atomicAdd(&g_cursor[d], 1);
    g_csr_src[pos] = s;
}

// ---------------- GEMM1 [N,256]x[256,256] bf16x3 MMA + fused alpha1 ---------
// tile 64x128, BK=16 (8 bf16x2 pairs), 8 warps (4m x 2n)
#define APSTRIDE 12    // 8 pairs + 4 pad (uint32)
#define BPSTRIDE 136   // 128 pairs(n) + 8 pad
#define NSTAGE   (IN_DIM / 16)   // 16

__global__ __launch_bounds__(256, 2)
void k_gemm1(const float* __restrict__ A, const float* __restrict__ B,
             const float* __restrict__ att_s, const float* __restrict__ att_d,
             int M) {
    // packed bf16x2 tiles: [buf][row][k-pair] / [buf][k-pair][n]
    __shared__ uint32_t Ah[2][64][APSTRIDE], Al[2][64][APSTRIDE];
    __shared__ uint32_t Bh[2][8][BPSTRIDE],  Bl[2][8][BPSTRIDE];

    int tid = threadIdx.x;
    int lane = tid & 31, warp = tid >> 5;
    int warp_m = warp & 3, warp_n = warp >> 2;
    int groupID = lane >> 2, tid4 = lane & 3;
    int rowBase = blockIdx.y * 64;
    int colBase = blockIdx.x * 128;

    // ---- load coordinates ----
    int a_r = tid >> 2, a_c4 = tid & 3;          // A: row, float4-chunk of k
    int a_row = rowBase + a_r;
    bool a_ok = a_row < M;
    const float* a_base = &A[(a_ok ? a_row : 0) * IN_DIM + a_c4 * 4];
    int b_p = tid >> 5, b_c4 = tid & 31;         // B: k-pair, float4-chunk of n

    float acc[8][4] = {};

    // ---- conversion+store helper (stage regs -> packed smem buf) ----
    auto stash = [&](int buf, float4 av, float4 bv0, float4 bv1) {
        // A: k pairs (4*a_c4, +1) and (4*a_c4+2, +3)
        uint32_t h0, l0, h1, l1;
        split_pair(av.x, av.y, h0, l0);
        split_pair(av.z, av.w, h1, l1);
        Ah[buf][a_r][a_c4 * 2] = h0; Ah[buf][a_r][a_c4 * 2 + 1] = h1;
        Al[buf][a_r][a_c4 * 2] = l0; Al[buf][a_r][a_c4 * 2 + 1] = l1;
        // B: pair p = b_p, n = b_c4*4..+3; bv0 = row 2p (even k), bv1 = 2p+1
        uint32_t bh[4], bl[4];
        split_pair(bv0.x, bv1.x, bh[0], bl[0]);
        split_pair(bv0.y, bv1.y, bh[1], bl[1]);
        split_pair(bv0.z, bv1.z, bh[2], bl[2]);
        split_pair(bv0.w, bv1.w, bh[3], bl[3]);
        *(uint4*)&Bh[buf][b_p][b_c4 * 4] = make_uint4(bh[0], bh[1], bh[2], bh[3]);
        *(uint4*)&Bl[buf][b_p][b_c4 * 4] = make_uint4(bl[0], bl[1], bl[2], bl[3]);
    };

    // ---- prologue: stage 0 ----
    {
        float4 av = make_float4(0.f, 0.f, 0.f, 0.f);
        if (a_ok) av = *(const float4*)a_base;
        float4 bv0 = *(const float4*)&B[(2 * b_p) * H1_DIM + colBase + b_c4 * 4];
        float4 bv1 = *(const float4*)&B[(2 * b_p + 1) * H1_DIM + colBase + b_c4 * 4];
        stash(0, av, bv0, bv1);
    }
    __syncthreads();

    for (int s = 0; s < NSTAGE; s++) {
        int cur = s & 1;
        float4 av, bv0, bv1;
        bool have_next = (s + 1 < NSTAGE);
        if (have_next) {
            int k0 = (s + 1) * 16;
            av = make_float4(0.f, 0.f, 0.f, 0.f);
            if (a_ok) av = *(const float4*)(a_base + k0);
            bv0 = *(const float4*)&B[(k0 + 2 * b_p) * H1_DIM + colBase + b_c4 * 4];
            bv1 = *(const float4*)&B[(k0 + 2 * b_p + 1) * H1_DIM + colBase + b_c4 * 4];
        }

        // ---- compute stage s (pure LDS + MMA) ----
        {
            int row = warp_m * 16 + groupID;
            uint32_t ah[4], al[4];
            ah[0] = Ah[cur][row][tid4];
            ah[1] = Ah[cur][row + 8][tid4];
            ah[2] = Ah[cur][row][tid4 + 4];
            ah[3] = Ah[cur][row + 8][tid4 + 4];
            al[0] = Al[cur][row][tid4];
            al[1] = Al[cur][row + 8][tid4];
            al[2] = Al[cur][row][tid4 + 4];
            al[3] = Al[cur][row + 8][tid4 + 4];
#pragma unroll
            for (int nt = 0; nt < 8; nt++) {
                int n = warp_n * 64 + nt * 8 + groupID;
                uint32_t bh0 = Bh[cur][tid4][n];
                uint32_t bh1 = Bh[cur][tid4 + 4][n];
                uint32_t bl0 = Bl[cur][tid4][n];
                uint32_t bl1 = Bl[cur][tid4 + 4][n];
                mma_bf16(acc[nt], ah[0], ah[1], ah[2], ah[3], bh0, bh1);
                mma_bf16(acc[nt], al[0], al[1], al[2], al[3], bh0, bh1);
                mma_bf16(acc[nt], ah[0], ah[1], ah[2], ah[3], bl0, bl1);
            }
        }

        if (have_next) stash(cur ^ 1, av, bv0, bv1);
        __syncthreads();
    }

    // ---- store h1 + fused alpha1 (warp covers one full head) ----
    int head = (colBase >> 6) + warp_n;
    float ss[2] = {0.f, 0.f}, sd[2] = {0.f, 0.f};
    int row0 = rowBase + warp_m * 16 + groupID;
    int row1 = row0 + 8;
#pragma unroll
    for (int nt = 0; nt < 8; nt++) {
        int col = colBase + warp_n * 64 + nt * 8 + tid4 * 2;
        float a_s0 = att_s[col], a_s1 = att_s[col + 1];
        float a_d0 = att_d[col], a_d1 = att_d[col + 1];
        float c0 = acc[nt][0], c1 = acc[nt][1];
        float c2 = acc[nt][2], c3 = acc[nt][3];
        if (row0 < M) *(float2*)&g_h1[row0 * H1_DIM + col] = make_float2(c0, c1);
        if (row1 < M) *(float2*)&g_h1[row1 * H1_DIM + col] = make_float2(c2, c3);
        ss[0] = fmaf(c0, a_s0, fmaf(c1, a_s1, ss[0]));
        ss[1] = fmaf(c2, a_s0, fmaf(c3, a_s1, ss[1]));
        sd[0] = fmaf(c0, a_d0, fmaf(c1, a_d1, sd[0]));
        sd[1] = fmaf(c2, a_d0, fmaf(c3, a_d1, sd[1]));
    }
#pragma unroll
    for (int hf = 0; hf < 2; hf++) {
#pragma unroll
        for (int off = 1; off < 4; off <<= 1) {
            ss[hf] += __shfl_xor_sync(0xffffffffu, ss[hf], off);
            sd[hf] += __shfl_xor_sync(0xffffffffu, sd[hf], off);
        }
        if (tid4 == 0) {
            int row = rowBase + warp_m * 16 + groupID + hf * 8;
            if (row < M) {
                g_as1[row * HEADS + head] = ss[hf];
                g_ad1[row * HEADS + head] = sd[hf];
            }
        }
    }
}

// ---- fused L1 single-pass softmax + aggregate + bias + relu (block/dst) ----
__global__ void k_agg1(const float* __restrict__ bias) {
    int n = blockIdx.x;
    int tid = threadIdx.x;
    int beg = g_rowptr[n];
    int deg = g_rowptr[n + 1] - beg;
    int lane = tid & 31, warp = tid >> 5;

    __shared__ int    sh_src[64];
    __shared__ float  sh_w[HEADS][64];
    __shared__ float4 sh_s[8];
    __shared__ float  sh_inv[HEADS];
    __shared__ float  sh_red[4][H1_DIM];

    float4 ad4 = *(const float4*)&g_ad1[n * HEADS];

    int g = tid >> 6, c4 = tid & 63, head = c4 >> 4;
    float4 acc = make_float4(0.f, 0.f, 0.f, 0.f);
    float4 sacc = make_float4(0.f, 0.f, 0.f, 0.f);

    for (int base = 0; base < deg; base += 64) {
        int len = min(64, deg - base);
        __syncthreads();
        if (tid < len) {
            int src = g_csr_src[beg + base + tid];
            sh_src[tid] = src;
            float4 as = *(const float4*)&g_as1[src * HEADS];
            float e0 = __expf(lrelu(as.x + ad4.x));
            float e1 = __expf(lrelu(as.y + ad4.y));
            float e2 = __expf(lrelu(as.z + ad4.z));
            float e3 = __expf(lrelu(as.w + ad4.w));
            sh_w[0][tid] = e0; sh_w[1][tid] = e1;
            sh_w[2][tid] = e2; sh_w[3][tid] = e3;
            sacc.x += e0; sacc.y += e1; sacc.z += e2; sacc.w += e3;
        }
        __syncthreads();
        for (int k = g; k < len; k += 4) {
            float w = sh_w[head][k];
            float4 v = *(const float4*)&g_h1[sh_src[k] * H1_DIM + c4 * 4];
            acc.x = fmaf(w, v.x, acc.x);
            acc.y = fmaf(w, v.y, acc.y);
            acc.z = fmaf(w, v.z, acc.z);
            acc.w = fmaf(w, v.w, acc.w);
        }
    }
#pragma unroll
    for (int off = 16; off > 0; off >>= 1) {
        sacc.x += __shfl_xor_sync(0xffffffffu, sacc.x, off);
        sacc.y += __shfl_xor_sync(0xffffffffu, sacc.y, off);
        sacc.z += __shfl_xor_sync(0xffffffffu, sacc.z, off);
        sacc.w += __shfl_xor_sync(0xffffffffu, sacc.w, off);
    }
    if (lane == 0) sh_s[warp] = sacc;
    __syncthreads();
    if (tid == 0) {
        float4 s = sh_s[0];
#pragma unroll
        for (int w = 1; w < 8; w++) {
            s.x += sh_s[w].x; s.y += sh_s[w].y;
            s.z += sh_s[w].z; s.w += sh_s[w].w;
        }
        sh_inv[0] = 1.f / s.x; sh_inv[1] = 1.f / s.y;
        sh_inv[2] = 1.f / s.z; sh_inv[3] = 1.f / s.w;
    }
    *(float4*)&sh_red[g][c4 * 4] = acc;
    __syncthreads();
    int c = tid;
    float v = (sh_red[0][c] + sh_red[1][c] + sh_red[2][c] + sh_red[3][c])
              * sh_inv[c >> 6] + bias[c];
    g_out1[n * H1_DIM + c] = v > 0.f ? v : 0.f;
}

// ---------------- GEMM2 [N,256]x[256,40] + fused alpha2 ---------------------
__global__ void k_gemm2(const float* __restrict__ W2,
                        const float* __restrict__ att_s,
                        const float* __restrict__ att_d, int M) {
    __shared__ float W2s[64 * OUT_DIM];
    __shared__ float hr[32 * 64];
    __shared__ float sh_o[32 * OUT_DIM];
    int tid = threadIdx.x;
    int rowBase = blockIdx.x * 32;
    float acc[5] = {0.f, 0.f, 0.f, 0.f, 0.f};
    for (int k0 = 0; k0 < H1_DIM; k0 += 64) {
        for (int idx = tid; idx < 64 * OUT_DIM; idx += 256)
            W2s[idx] = W2[(k0 + idx / OUT_DIM) * OUT_DIM + idx % OUT_DIM];
        for (int f = tid; f < 512; f += 256) {
            int r = f >> 4, c4 = f & 15;
            int row = rowBase + r;
            float4 v = make_float4(0.f, 0.f, 0.f, 0.f);
            if (row < M) v = *(const float4*)&g_out1[row * H1_DIM + k0 + c4 * 4];
            *(float4*)&hr[r * 64 + c4 * 4] = v;
        }
        __syncthreads();
#pragma unroll
        for (int oi = 0; oi < 5; oi++) {
            int out_idx = tid + oi * 256;
            int r = out_idx / OUT_DIM, c = out_idx % OUT_DIM;
            float a = acc[oi];
#pragma unroll 8
            for (int k = 0; k < 64; k++)
                a = fmaf(hr[r * 64 + k], W2s[k * OUT_DIM + c], a);
            acc[oi] = a;
        }
        __syncthreads();
    }
#pragma unroll
    for (int oi = 0; oi < 5; oi++) {
        int out_idx = tid + oi * 256;
        int r = out_idx / OUT_DIM, c = out_idx % OUT_DIM;
        int row = rowBase + r;
        sh_o[out_idx] = acc[oi];
        if (row < M) g_h2[row * OUT_DIM + c] = acc[oi];
    }
    __syncthreads();
    if (tid < 32) {
        int row = rowBase + tid;
        if (row < M) {
            float ss = 0.f, sd = 0.f;
#pragma unroll
            for (int k = 0; k < OUT_DIM; k++) {
                float v = sh_o[tid * OUT_DIM + k];
                ss = fmaf(v, att_s[k], ss);
                sd = fmaf(v, att_d[k], sd);
            }
            g_as2[row] = ss;
            g_ad2[row] = sd;
        }
    }
}

// ---- fused L2 single-pass softmax + aggregate + bias + log_softmax ---------
__global__ void k_agg2(const float* __restrict__ bias, float* __restrict__ out) {
    int n = blockIdx.x;
    int tid = threadIdx.x;
    int beg = g_rowptr[n];
    int deg = g_rowptr[n + 1] - beg;
    int lane = tid & 31, warp = tid >> 5;

    __shared__ int   sh_src[64];
    __shared__ float sh_w[64];
    __shared__ float sh_s[4];
    __shared__ float sh_inv;
    __shared__ float sh_part[128];
    __shared__ float sh_row[OUT_DIM];
    __shared__ float sh_lse;

    float adn = g_ad2[n];

    int eo = tid >> 6, c = tid & 63;
    float acc = 0.f, sacc = 0.f;
    for (int base = 0; base < deg; base += 64) {
        int len = min(64, deg - base);
        __syncthreads();
        if (tid < len) {
            int src = g_csr_src[beg + base + tid];
            sh_src[tid] = src;
            float e = __expf(lrelu(g_as2[src] + adn));
            sh_w[tid] = e;
            sacc += e;
        }
        __syncthreads();
        if (c < OUT_DIM) {
            for (int k = eo; k < len; k += 2)
                acc = fmaf(sh_w[k], g_h2[sh_src[k] * OUT_DIM + c], acc);
        }
    }
#pragma unroll
    for (int off = 16; off > 0; off >>= 1)
        sacc += __shfl_xor_sync(0xffffffffu, sacc, off);
    if (lane == 0) sh_s[warp] = sacc;
    sh_part[tid] = acc;
    __syncthreads();
    if (tid == 0) sh_inv = 1.f / (sh_s[0] + sh_s[1] + sh_s[2] + sh_s[3]);
    __syncthreads();
    if (tid < OUT_DIM)
        sh_row[tid] = (sh_part[tid] + sh_part[tid + 64]) * sh_inv + bias[tid];
    __syncthreads();
    if (tid == 0) {
        float m = -1e30f;
#pragma unroll
        for (int k = 0; k < OUT_DIM; k++) m = fmaxf(m, sh_row[k]);
        float s = 0.f;
#pragma unroll
        for (int k = 0; k < OUT_DIM; k++) s += __expf(sh_row[k] - m);
        sh_lse = m + logf(s);
    }
    __syncthreads();
    if (tid < OUT_DIM) out[n * OUT_DIM + tid] = sh_row[tid] - sh_lse;
}

// ----------------------------------------------------------------------------
extern "C" void kernel_launch(void* const* d_in, const int* in_sizes, int n_in,
                              void* d_out, int out_size) {
    const float* x   = (const float*)d_in[0];
    const int*   ei  = (const int*)d_in[1];
    const float* W1  = (const float*)d_in[2];
    const float* as1 = (const float*)d_in[3];
    const float* ad1 = (const float*)d_in[4];
    const float* b1  = (const float*)d_in[5];
    const float* W2  = (const float*)d_in[6];
    const float* as2 = (const float*)d_in[7];
    const float* ad2 = (const float*)d_in[8];
    const float* b2  = (const float*)d_in[9];
    float* out = (float*)d_out;

    int N  = in_sizes[0] / IN_DIM;
    int E  = in_sizes[1] / 2;
    int ET = E + N;

    // CSR build
    k_deg<<<(E + 255) / 256, 256>>>(ei, E);
    k_scan<<<1, 1024>>>(N);
    k_scatter<<<(ET + 255) / 256, 256>>>(ei, E, ET);

    // layer 1
    {
        dim3 grid(H1_DIM / 128, (N + 63) / 64);
        k_gemm1<<<grid, 256>>>(x, W1, as1, ad1, N);
    }
    k_agg1<<<N, 256>>>(b1);

    // layer 2
    k_gemm2<<<(N + 31) / 32, 256>>>(W2, as2, ad2, N);
    k_agg2<<<N, 128>>>(b2, out);
}

// round 13
// speedup vs baseline: 1.1976x; 1.0247x over previous
#include <cuda_runtime.h>
#include <cuda_bf16.h>
#include <cuda_fp16.h>
#include <math.h>
#include <stdint.h>

// ----------------------------------------------------------------------------
// SimpleGAT R13: h1 stored fp16-only (halves the L2 gather traffic in k_agg1,
// the dominant kernel). GEMM1 = bf16x3 MMA from R12. Rest identical.
// ----------------------------------------------------------------------------

#define MAXN 10000
#define MAXE 320000
#define MAXET (MAXE + MAXN)

#define IN_DIM 256
#define H1_DIM 256
#define HEADS 4
#define HID 64
#define OUT_DIM 40

// ------------------------------ scratch ------------------------------------
__device__ __align__(16) __half g_h1h[MAXN * H1_DIM];   // fp16 h1 (gather source)
__device__ __align__(16) float g_out1[MAXN * H1_DIM];
__device__ __align__(16) float g_as1[MAXN * HEADS];
__device__ __align__(16) float g_ad1[MAXN * HEADS];

__device__ __align__(16) float g_h2[MAXN * OUT_DIM];
__device__ float g_as2[MAXN];
__device__ float g_ad2[MAXN];

__device__ int g_deg[MAXN];        // static-zero; re-zeroed by k_scatter each run
__device__ int g_rowptr[MAXN + 1];
__device__ int g_cursor[MAXN];
__device__ int g_csr_src[MAXET];

__device__ __forceinline__ float lrelu(float t) { return t > 0.f ? t : 0.2f * t; }

// pack truncated-bf16 his of (x=k_even, y=k_odd): lower half = x_hi
__device__ __forceinline__ uint32_t pack_hi(uint32_t ux, uint32_t uy) {
    uint32_t d;
    asm("prmt.b32 %0, %1, %2, 0x7632;" : "=r"(d) : "r"(ux), "r"(uy));
    return d;
}
__device__ __forceinline__ uint32_t pack_lo(float le, float lo) {
    uint32_t d;
    asm("cvt.rn.bf16x2.f32 %0, %1, %2;" : "=r"(d) : "f"(lo), "f"(le));
    return d;
}
__device__ __forceinline__ void split_pair(float x, float y,
                                           uint32_t& hi, uint32_t& lo) {
    uint32_t ux = __float_as_uint(x), uy = __float_as_uint(y);
    hi = pack_hi(ux, uy);
    float xr = x - __uint_as_float(ux & 0xFFFF0000u);
    float yr = y - __uint_as_float(uy & 0xFFFF0000u);
    lo = pack_lo(xr, yr);
}

__device__ __forceinline__ void mma_bf16(float c[4], uint32_t a0, uint32_t a1,
                                         uint32_t a2, uint32_t a3,
                                         uint32_t b0, uint32_t b1) {
    asm volatile(
        "mma.sync.aligned.m16n8k16.row.col.f32.bf16.bf16.f32 "
        "{%0,%1,%2,%3}, {%4,%5,%6,%7}, {%8,%9}, {%0,%1,%2,%3};"
        : "+f"(c[0]), "+f"(c[1]), "+f"(c[2]), "+f"(c[3])
        : "r"(a0), "r"(a1), "r"(a2), "r"(a3), "r"(b0), "r"(b1));
}

// ------------------------------ CSR build -----------------------------------
__global__ void k_deg(const int* __restrict__ ei, int E) {
    int e = blockIdx.x * blockDim.x + threadIdx.x;
    if (e < E) atomicAdd(&g_deg[ei[E + e]], 1);
}

__global__ void k_scan(int N) {
    int tid = threadIdx.x;
    const int C = (N + 1023) >> 10;
    int start = tid * C;
    int local[16];
    int sum = 0;
#pragma unroll
    for (int j = 0; j < 16; j++) {
        if (j >= C) break;
        int i = start + j;
        int v = (i < N) ? (g_deg[i] + 1) : 0;   // +1 self loop
        local[j] = sum;
        sum += v;
    }
    int lane = tid & 31, warp = tid >> 5;
    int inc = sum;
#pragma unroll
    for (int off = 1; off < 32; off <<= 1) {
        int t = __shfl_up_sync(0xffffffffu, inc, off);
        if (lane >= off) inc += t;
    }
    __shared__ int wtot[32];
    if (lane == 31) wtot[warp] = inc;
    __syncthreads();
    if (warp == 0) {
        int v = wtot[lane];
#pragma unroll
        for (int off = 1; off < 32; off <<= 1) {
            int t = __shfl_up_sync(0xffffffffu, v, off);
            if (lane >= off) v += t;
        }
        wtot[lane] = v;
    }
    __syncthreads();
    int carry = (warp > 0 ? wtot[warp - 1] : 0) + (inc - sum);
#pragma unroll
    for (int j = 0; j < 16; j++) {
        if (j >= C) break;
        int i = start + j;
        if (i < N) {
            int e = carry + local[j];
            g_rowptr[i] = e;
            g_cursor[i] = e;
        }
    }
    if (tid == 1023) g_rowptr[N] = wtot[31];
}

__global__ void k_scatter(const int* __restrict__ ei, int E, int ET) {
    int e = blockIdx.x * blockDim.x + threadIdx.x;
    if (e >= ET) return;
    int s, d;
    if (e < E) { s = ei[e]; d = ei[E + e]; }
    else       { s = d = e - E; g_deg[d] = 0; }   // reset for next launch
    int pos = atomicAdd(&g_cursor[d], 1);
    g_csr_src[pos] = s;
}

// ---------------- GEMM1 [N,256]x[256,256] bf16x3 MMA + fused alpha1 ---------
// tile 64x128, BK=16 (8 bf16x2 pairs), 8 warps (4m x 2n)
#define APSTRIDE 12
#define BPSTRIDE 136
#define NSTAGE   (IN_DIM / 16)   // 16

__global__ __launch_bounds__(256, 2)
void k_gemm1(const float* __restrict__ A, const float* __restrict__ B,
             const float* __restrict__ att_s, const float* __restrict__ att_d,
             int M) {
    __shared__ uint32_t Ah[2][64][APSTRIDE], Al[2][64][APSTRIDE];
    __shared__ uint32_t Bh[2][8][BPSTRIDE],  Bl[2][8][BPSTRIDE];

    int tid = threadIdx.x;
    int lane = tid & 31, warp = tid >> 5;
    int warp_m = warp & 3, warp_n = warp >> 2;
    int groupID = lane >> 2, tid4 = lane & 3;
    int rowBase = blockIdx.y * 64;
    int colBase = blockIdx.x * 128;

    int a_r = tid >> 2, a_c4 = tid & 3;
    int a_row = rowBase + a_r;
    bool a_ok = a_row < M;
    const float* a_base = &A[(a_ok ? a_row : 0) * IN_DIM + a_c4 * 4];
    int b_p = tid >> 5, b_c4 = tid & 31;

    float acc[8][4] = {};

    auto stash = [&](int buf, float4 av, float4 bv0, float4 bv1) {
        uint32_t h0, l0, h1, l1;
        split_pair(av.x, av.y, h0, l0);
        split_pair(av.z, av.w, h1, l1);
        Ah[buf][a_r][a_c4 * 2] = h0; Ah[buf][a_r][a_c4 * 2 + 1] = h1;
        Al[buf][a_r][a_c4 * 2] = l0; Al[buf][a_r][a_c4 * 2 + 1] = l1;
        uint32_t bh[4], bl[4];
        split_pair(bv0.x, bv1.x, bh[0], bl[0]);
        split_pair(bv0.y, bv1.y, bh[1], bl[1]);
        split_pair(bv0.z, bv1.z, bh[2], bl[2]);
        split_pair(bv0.w, bv1.w, bh[3], bl[3]);
        *(uint4*)&Bh[buf][b_p][b_c4 * 4] = make_uint4(bh[0], bh[1], bh[2], bh[3]);
        *(uint4*)&Bl[buf][b_p][b_c4 * 4] = make_uint4(bl[0], bl[1], bl[2], bl[3]);
    };

    {
        float4 av = make_float4(0.f, 0.f, 0.f, 0.f);
        if (a_ok) av = *(const float4*)a_base;
        float4 bv0 = *(const float4*)&B[(2 * b_p) * H1_DIM + colBase + b_c4 * 4];
        float4 bv1 = *(const float4*)&B[(2 * b_p + 1) * H1_DIM + colBase + b_c4 * 4];
        stash(0, av, bv0, bv1);
    }
    __syncthreads();

    for (int s = 0; s < NSTAGE; s++) {
        int cur = s & 1;
        float4 av, bv0, bv1;
        bool have_next = (s + 1 < NSTAGE);
        if (have_next) {
            int k0 = (s + 1) * 16;
            av = make_float4(0.f, 0.f, 0.f, 0.f);
            if (a_ok) av = *(const float4*)(a_base + k0);
            bv0 = *(const float4*)&B[(k0 + 2 * b_p) * H1_DIM + colBase + b_c4 * 4];
            bv1 = *(const float4*)&B[(k0 + 2 * b_p + 1) * H1_DIM + colBase + b_c4 * 4];
        }
        {
            int row = warp_m * 16 + groupID;
            uint32_t ah[4], al[4];
            ah[0] = Ah[cur][row][tid4];
            ah[1] = Ah[cur][row + 8][tid4];
            ah[2] = Ah[cur][row][tid4 + 4];
            ah[3] = Ah[cur][row + 8][tid4 + 4];
            al[0] = Al[cur][row][tid4];
            al[1] = Al[cur][row + 8][tid4];
            al[2] = Al[cur][row][tid4 + 4];
            al[3] = Al[cur][row + 8][tid4 + 4];
#pragma unroll
            for (int nt = 0; nt < 8; nt++) {
                int n = warp_n * 64 + nt * 8 + groupID;
                uint32_t bh0 = Bh[cur][tid4][n];
                uint32_t bh1 = Bh[cur][tid4 + 4][n];
                uint32_t bl0 = Bl[cur][tid4][n];
                uint32_t bl1 = Bl[cur][tid4 + 4][n];
                mma_bf16(acc[nt], ah[0], ah[1], ah[2], ah[3], bh0, bh1);
                mma_bf16(acc[nt], al[0], al[1], al[2], al[3], bh0, bh1);
                mma_bf16(acc[nt], ah[0], ah[1], ah[2], ah[3], bl0, bl1);
            }
        }
        if (have_next) stash(cur ^ 1, av, bv0, bv1);
        __syncthreads();
    }

    // ---- store h1 (fp16) + fused alpha1 ----
    int head = (colBase >> 6) + warp_n;
    float ss[2] = {0.f, 0.f}, sd[2] = {0.f, 0.f};
    int row0 = rowBase + warp_m * 16 + groupID;
    int row1 = row0 + 8;
#pragma unroll
    for (int nt = 0; nt < 8; nt++) {
        int col = colBase + warp_n * 64 + nt * 8 + tid4 * 2;
        float a_s0 = att_s[col], a_s1 = att_s[col + 1];
        float a_d0 = att_d[col], a_d1 = att_d[col + 1];
        float c0 = acc[nt][0], c1 = acc[nt][1];
        float c2 = acc[nt][2], c3 = acc[nt][3];
        if (row0 < M)
            *(__half2*)&g_h1h[row0 * H1_DIM + col] = __floats2half2_rn(c0, c1);
        if (row1 < M)
            *(__half2*)&g_h1h[row1 * H1_DIM + col] = __floats2half2_rn(c2, c3);
        ss[0] = fmaf(c0, a_s0, fmaf(c1, a_s1, ss[0]));
        ss[1] = fmaf(c2, a_s0, fmaf(c3, a_s1, ss[1]));
        sd[0] = fmaf(c0, a_d0, fmaf(c1, a_d1, sd[0]));
        sd[1] = fmaf(c2, a_d0, fmaf(c3, a_d1, sd[1]));
    }
#pragma unroll
    for (int hf = 0; hf < 2; hf++) {
#pragma unroll
        for (int off = 1; off < 4; off <<= 1) {
            ss[hf] += __shfl_xor_sync(0xffffffffu, ss[hf], off);
            sd[hf] += __shfl_xor_sync(0xffffffffu, sd[hf], off);
        }
        if (tid4 == 0) {
            int row = rowBase + warp_m * 16 + groupID + hf * 8;
            if (row < M) {
                g_as1[row * HEADS + head] = ss[hf];
                g_ad1[row * HEADS + head] = sd[hf];
            }
        }
    }
}

// ---- fused L1 single-pass softmax + aggregate + bias + relu (block/dst) ----
// gathers fp16 h1, accumulates fp32
__global__ void k_agg1(const float* __restrict__ bias) {
    int n = blockIdx.x;
    int tid = threadIdx.x;
    int beg = g_rowptr[n];
    int deg = g_rowptr[n + 1] - beg;
    int lane = tid & 31, warp = tid >> 5;

    __shared__ int    sh_src[64];
    __shared__ float  sh_w[HEADS][64];
    __shared__ float4 sh_s[8];
    __shared__ float  sh_inv[HEADS];
    __shared__ float  sh_red[4][H1_DIM];

    float4 ad4 = *(const float4*)&g_ad1[n * HEADS];

    int g = tid >> 6, c4 = tid & 63, head = c4 >> 4;
    float4 acc = make_float4(0.f, 0.f, 0.f, 0.f);
    float4 sacc = make_float4(0.f, 0.f, 0.f, 0.f);

    for (int base = 0; base < deg; base += 64) {
        int len = min(64, deg - base);
        __syncthreads();
        if (tid < len) {
            int src = g_csr_src[beg + base + tid];
            sh_src[tid] = src;
            float4 as = *(const float4*)&g_as1[src * HEADS];
            float e0 = __expf(lrelu(as.x + ad4.x));
            float e1 = __expf(lrelu(as.y + ad4.y));
            float e2 = __expf(lrelu(as.z + ad4.z));
            float e3 = __expf(lrelu(as.w + ad4.w));
            sh_w[0][tid] = e0; sh_w[1][tid] = e1;
            sh_w[2][tid] = e2; sh_w[3][tid] = e3;
            sacc.x += e0; sacc.y += e1; sacc.z += e2; sacc.w += e3;
        }
        __syncthreads();
        for (int k = g; k < len; k += 4) {
            float w = sh_w[head][k];
            uint2 raw = *(const uint2*)&g_h1h[sh_src[k] * H1_DIM + c4 * 4];
            float2 f0 = __half22float2(*(__half2*)&raw.x);
            float2 f1 = __half22float2(*(__half2*)&raw.y);
            acc.x = fmaf(w, f0.x, acc.x);
            acc.y = fmaf(w, f0.y, acc.y);
            acc.z = fmaf(w, f1.x, acc.z);
            acc.w = fmaf(w, f1.y, acc.w);
        }
    }
#pragma unroll
    for (int off = 16; off > 0; off >>= 1) {
        sacc.x += __shfl_xor_sync(0xffffffffu, sacc.x, off);
        sacc.y += __shfl_xor_sync(0xffffffffu, sacc.y, off);
        sacc.z += __shfl_xor_sync(0xffffffffu, sacc.z, off);
        sacc.w += __shfl_xor_sync(0xffffffffu, sacc.w, off);
    }
    if (lane == 0) sh_s[warp] = sacc;
    __syncthreads();
    if (tid == 0) {
        float4 s = sh_s[0];
#pragma unroll
        for (int w = 1; w < 8; w++) {
            s.x += sh_s[w].x; s.y += sh_s[w].y;
            s.z += sh_s[w].z; s.w += sh_s[w].w;
        }
        sh_inv[0] = 1.f / s.x; sh_inv[1] = 1.f / s.y;
        sh_inv[2] = 1.f / s.z; sh_inv[3] = 1.f / s.w;
    }
    *(float4*)&sh_red[g][c4 * 4] = acc;
    __syncthreads();
    int c = tid;
    float v = (sh_red[0][c] + sh_red[1][c] + sh_red[2][c] + sh_red[3][c])
              * sh_inv[c >> 6] + bias[c];
    g_out1[n * H1_DIM + c] = v > 0.f ? v : 0.f;
}

// ---------------- GEMM2 [N,256]x[256,40] + fused alpha2 ---------------------
__global__ void k_gemm2(const float* __restrict__ W2,
                        const float* __restrict__ att_s,
                        const float* __restrict__ att_d, int M) {
    __shared__ float W2s[64 * OUT_DIM];
    __shared__ float hr[32 * 64];
    __shared__ float sh_o[32 * OUT_DIM];
    int tid = threadIdx.x;
    int rowBase = blockIdx.x * 32;
    float acc[5] = {0.f, 0.f, 0.f, 0.f, 0.f};
    for (int k0 = 0; k0 < H1_DIM; k0 += 64) {
        for (int idx = tid; idx < 64 * OUT_DIM; idx += 256)
            W2s[idx] = W2[(k0 + idx / OUT_DIM) * OUT_DIM + idx % OUT_DIM];
        for (int f = tid; f < 512; f += 256) {
            int r = f >> 4, c4 = f & 15;
            int row = rowBase + r;
            float4 v = make_float4(0.f, 0.f, 0.f, 0.f);
            if (row < M) v = *(const float4*)&g_out1[row * H1_DIM + k0 + c4 * 4];
            *(float4*)&hr[r * 64 + c4 * 4] = v;
        }
        __syncthreads();
#pragma unroll
        for (int oi = 0; oi < 5; oi++) {
            int out_idx = tid + oi * 256;
            int r = out_idx / OUT_DIM, c = out_idx % OUT_DIM;
            float a = acc[oi];
#pragma unroll 8
            for (int k = 0; k < 64; k++)
                a = fmaf(hr[r * 64 + k], W2s[k * OUT_DIM + c], a);
            acc[oi] = a;
        }
        __syncthreads();
    }
#pragma unroll
    for (int oi = 0; oi < 5; oi++) {
        int out_idx = tid + oi * 256;
        int r = out_idx / OUT_DIM, c = out_idx % OUT_DIM;
        int row = rowBase + r;
        sh_o[out_idx] = acc[oi];
        if (row < M) g_h2[row * OUT_DIM + c] = acc[oi];
    }
    __syncthreads();
    if (tid < 32) {
        int row = rowBase + tid;
        if (row < M) {
            float ss = 0.f, sd = 0.f;
#pragma unroll
            for (int k = 0; k < OUT_DIM; k++) {
                float v = sh_o[tid * OUT_DIM + k];
                ss = fmaf(v, att_s[k], ss);
                sd = fmaf(v, att_d[k], sd);
            }
            g_as2[row] = ss;
            g_ad2[row] = sd;
        }
    }
}

// ---- fused L2 single-pass softmax + aggregate + bias + log_softmax ---------
__global__ void k_agg2(const float* __restrict__ bias, float* __restrict__ out) {
    int n = blockIdx.x;
    int tid = threadIdx.x;
    int beg = g_rowptr[n];
    int deg = g_rowptr[n + 1] - beg;
    int lane = tid & 31, warp = tid >> 5;

    __shared__ int   sh_src[64];
    __shared__ float sh_w[64];
    __shared__ float sh_s[4];
    __shared__ float sh_inv;
    __shared__ float sh_part[128];
    __shared__ float sh_row[OUT_DIM];
    __shared__ float sh_lse;

    float adn = g_ad2[n];

    int eo = tid >> 6, c = tid & 63;
    float acc = 0.f, sacc = 0.f;
    for (int base = 0; base < deg; base += 64) {
        int len = min(64, deg - base);
        __syncthreads();
        if (tid < len) {
            int src = g_csr_src[beg + base + tid];
            sh_src[tid] = src;
            float e = __expf(lrelu(g_as2[src] + adn));
            sh_w[tid] = e;
            sacc += e;
        }
        __syncthreads();
        if (c < OUT_DIM) {
            for (int k = eo; k < len; k += 2)
                acc = fmaf(sh_w[k], g_h2[sh_src[k] * OUT_DIM + c], acc);
        }
    }
#pragma unroll
    for (int off = 16; off > 0; off >>= 1)
        sacc += __shfl_xor_sync(0xffffffffu, sacc, off);
    if (lane == 0) sh_s[warp] = sacc;
    sh_part[tid] = acc;
    __syncthreads();
    if (tid == 0) sh_inv = 1.f / (sh_s[0] + sh_s[1] + sh_s[2] + sh_s[3]);
    __syncthreads();
    if (tid < OUT_DIM)
        sh_row[tid] = (sh_part[tid] + sh_part[tid + 64]) * sh_inv + bias[tid];
    __syncthreads();
    if (tid == 0) {
        float m = -1e30f;
#pragma unroll
        for (int k = 0; k < OUT_DIM; k++) m = fmaxf(m, sh_row[k]);
        float s = 0.f;
#pragma unroll
        for (int k = 0; k < OUT_DIM; k++) s += __expf(sh_row[k] - m);
        sh_lse = m + logf(s);
    }
    __syncthreads();
    if (tid < OUT_DIM) out[n * OUT_DIM + tid] = sh_row[tid] - sh_lse;
}

// ----------------------------------------------------------------------------
extern "C" void kernel_launch(void* const* d_in, const int* in_sizes, int n_in,
                              void* d_out, int out_size) {
    const float* x   = (const float*)d_in[0];
    const int*   ei  = (const int*)d_in[1];
    const float* W1  = (const float*)d_in[2];
    const float* as1 = (const float*)d_in[3];
    const float* ad1 = (const float*)d_in[4];
    const float* b1  = (const float*)d_in[5];
    const float* W2  = (const float*)d_in[6];
    const float* as2 = (const float*)d_in[7];
    const float* ad2 = (const float*)d_in[8];
    const float* b2  = (const float*)d_in[9];
    float* out = (float*)d_out;

    int N  = in_sizes[0] / IN_DIM;
    int E  = in_sizes[1] / 2;
    int ET = E + N;

    // CSR build
    k_deg<<<(E + 255) / 256, 256>>>(ei, E);
    k_scan<<<1, 1024>>>(N);
    k_scatter<<<(ET + 255) / 256, 256>>>(ei, E, ET);

    // layer 1
    {
        dim3 grid(H1_DIM / 128, (N + 63) / 64);
        k_gemm1<<<grid, 256>>>(x, W1, as1, ad1, N);
    }
    k_agg1<<<N, 256>>>(b1);

    // layer 2
    k_gemm2<<<(N + 31) / 32, 256>>>(W2, as2, ad2, N);
    k_agg2<<<N, 128>>>(b2, out);
}

// round 14
// speedup vs baseline: 1.2496x; 1.0435x over previous
#include <cuda_runtime.h>
#include <cuda_bf16.h>
#include <cuda_fp16.h>
#include <math.h>
#include <stdint.h>

// ----------------------------------------------------------------------------
// SimpleGAT R14: fp32 h1 restored (no CVTs in gather), agg1 = warp-per-edge
// 8ch/thread; gemm2 register-blocked (row,5-col) with shuffle alpha2.
// GEMM1 = bf16x3 MMA pipeline from R12.
// ----------------------------------------------------------------------------

#define MAXN 10000
#define MAXE 320000
#define MAXET (MAXE + MAXN)

#define IN_DIM 256
#define H1_DIM 256
#define HEADS 4
#define HID 64
#define OUT_DIM 40

// ------------------------------ scratch ------------------------------------
__device__ __align__(16) float g_h1[MAXN * H1_DIM];
__device__ __align__(16) float g_out1[MAXN * H1_DIM];
__device__ __align__(16) float g_as1[MAXN * HEADS];
__device__ __align__(16) float g_ad1[MAXN * HEADS];

__device__ __align__(16) float g_h2[MAXN * OUT_DIM];
__device__ float g_as2[MAXN];
__device__ float g_ad2[MAXN];

__device__ int g_deg[MAXN];        // static-zero; re-zeroed by k_scatter each run
__device__ int g_rowptr[MAXN + 1];
__device__ int g_cursor[MAXN];
__device__ int g_csr_src[MAXET];

__device__ __forceinline__ float lrelu(float t) { return t > 0.f ? t : 0.2f * t; }

__device__ __forceinline__ uint32_t pack_hi(uint32_t ux, uint32_t uy) {
    uint32_t d;
    asm("prmt.b32 %0, %1, %2, 0x7632;" : "=r"(d) : "r"(ux), "r"(uy));
    return d;
}
__device__ __forceinline__ uint32_t pack_lo(float le, float lo) {
    uint32_t d;
    asm("cvt.rn.bf16x2.f32 %0, %1, %2;" : "=r"(d) : "f"(lo), "f"(le));
    return d;
}
__device__ __forceinline__ void split_pair(float x, float y,
                                           uint32_t& hi, uint32_t& lo) {
    uint32_t ux = __float_as_uint(x), uy = __float_as_uint(y);
    hi = pack_hi(ux, uy);
    float xr = x - __uint_as_float(ux & 0xFFFF0000u);
    float yr = y - __uint_as_float(uy & 0xFFFF0000u);
    lo = pack_lo(xr, yr);
}

__device__ __forceinline__ void mma_bf16(float c[4], uint32_t a0, uint32_t a1,
                                         uint32_t a2, uint32_t a3,
                                         uint32_t b0, uint32_t b1) {
    asm volatile(
        "mma.sync.aligned.m16n8k16.row.col.f32.bf16.bf16.f32 "
        "{%0,%1,%2,%3}, {%4,%5,%6,%7}, {%8,%9}, {%0,%1,%2,%3};"
        : "+f"(c[0]), "+f"(c[1]), "+f"(c[2]), "+f"(c[3])
        : "r"(a0), "r"(a1), "r"(a2), "r"(a3), "r"(b0), "r"(b1));
}

// ------------------------------ CSR build -----------------------------------
__global__ void k_deg(const int* __restrict__ ei, int E) {
    int e = blockIdx.x * blockDim.x + threadIdx.x;
    if (e < E) atomicAdd(&g_deg[ei[E + e]], 1);
}

__global__ void k_scan(int N) {
    int tid = threadIdx.x;
    const int C = (N + 1023) >> 10;
    int start = tid * C;
    int local[16];
    int sum = 0;
#pragma unroll
    for (int j = 0; j < 16; j++) {
        if (j >= C) break;
        int i = start + j;
        int v = (i < N) ? (g_deg[i] + 1) : 0;   // +1 self loop
        local[j] = sum;
        sum += v;
    }
    int lane = tid & 31, warp = tid >> 5;
    int inc = sum;
#pragma unroll
    for (int off = 1; off < 32; off <<= 1) {
        int t = __shfl_up_sync(0xffffffffu, inc, off);
        if (lane >= off) inc += t;
    }
    __shared__ int wtot[32];
    if (lane == 31) wtot[warp] = inc;
    __syncthreads();
    if (warp == 0) {
        int v = wtot[lane];
#pragma unroll
        for (int off = 1; off < 32; off <<= 1) {
            int t = __shfl_up_sync(0xffffffffu, v, off);
            if (lane >= off) v += t;
        }
        wtot[lane] = v;
    }
    __syncthreads();
    int carry = (warp > 0 ? wtot[warp - 1] : 0) + (inc - sum);
#pragma unroll
    for (int j = 0; j < 16; j++) {
        if (j >= C) break;
        int i = start + j;
        if (i < N) {
            int e = carry + local[j];
            g_rowptr[i] = e;
            g_cursor[i] = e;
        }
    }
    if (tid == 1023) g_rowptr[N] = wtot[31];
}

__global__ void k_scatter(const int* __restrict__ ei, int E, int ET) {
    int e = blockIdx.x * blockDim.x + threadIdx.x;
    if (e >= ET) return;
    int s, d;
    if (e < E) { s = ei[e]; d = ei[E + e]; }
    else       { s = d = e - E; g_deg[d] = 0; }   // reset for next launch
    int pos = atomicAdd(&g_cursor[d], 1);
    g_csr_src[pos] = s;
}

// ---------------- GEMM1 [N,256]x[256,256] bf16x3 MMA + fused alpha1 ---------
#define APSTRIDE 12
#define BPSTRIDE 136
#define NSTAGE   (IN_DIM / 16)   // 16

__global__ __launch_bounds__(256, 2)
void k_gemm1(const float* __restrict__ A, const float* __restrict__ B,
             const float* __restrict__ att_s, const float* __restrict__ att_d,
             int M) {
    __shared__ uint32_t Ah[2][64][APSTRIDE], Al[2][64][APSTRIDE];
    __shared__ uint32_t Bh[2][8][BPSTRIDE],  Bl[2][8][BPSTRIDE];

    int tid = threadIdx.x;
    int lane = tid & 31, warp = tid >> 5;
    int warp_m = warp & 3, warp_n = warp >> 2;
    int groupID = lane >> 2, tid4 = lane & 3;
    int rowBase = blockIdx.y * 64;
    int colBase = blockIdx.x * 128;

    int a_r = tid >> 2, a_c4 = tid & 3;
    int a_row = rowBase + a_r;
    bool a_ok = a_row < M;
    const float* a_base = &A[(a_ok ? a_row : 0) * IN_DIM + a_c4 * 4];
    int b_p = tid >> 5, b_c4 = tid & 31;

    float acc[8][4] = {};

    auto stash = [&](int buf, float4 av, float4 bv0, float4 bv1) {
        uint32_t h0, l0, h1, l1;
        split_pair(av.x, av.y, h0, l0);
        split_pair(av.z, av.w, h1, l1);
        Ah[buf][a_r][a_c4 * 2] = h0; Ah[buf][a_r][a_c4 * 2 + 1] = h1;
        Al[buf][a_r][a_c4 * 2] = l0; Al[buf][a_r][a_c4 * 2 + 1] = l1;
        uint32_t bh[4], bl[4];
        split_pair(bv0.x, bv1.x, bh[0], bl[0]);
        split_pair(bv0.y, bv1.y, bh[1], bl[1]);
        split_pair(bv0.z, bv1.z, bh[2], bl[2]);
        split_pair(bv0.w, bv1.w, bh[3], bl[3]);
        *(uint4*)&Bh[buf][b_p][b_c4 * 4] = make_uint4(bh[0], bh[1], bh[2], bh[3]);
        *(uint4*)&Bl[buf][b_p][b_c4 * 4] = make_uint4(bl[0], bl[1], bl[2], bl[3]);
    };

    {
        float4 av = make_float4(0.f, 0.f, 0.f, 0.f);
        if (a_ok) av = *(const float4*)a_base;
        float4 bv0 = *(const float4*)&B[(2 * b_p) * H1_DIM + colBase + b_c4 * 4];
        float4 bv1 = *(const float4*)&B[(2 * b_p + 1) * H1_DIM + colBase + b_c4 * 4];
        stash(0, av, bv0, bv1);
    }
    __syncthreads();

    for (int s = 0; s < NSTAGE; s++) {
        int cur = s & 1;
        float4 av, bv0, bv1;
        bool have_next = (s + 1 < NSTAGE);
        if (have_next) {
            int k0 = (s + 1) * 16;
            av = make_float4(0.f, 0.f, 0.f, 0.f);
            if (a_ok) av = *(const float4*)(a_base + k0);
            bv0 = *(const float4*)&B[(k0 + 2 * b_p) * H1_DIM + colBase + b_c4 * 4];
            bv1 = *(const float4*)&B[(k0 + 2 * b_p + 1) * H1_DIM + colBase + b_c4 * 4];
        }
        {
            int row = warp_m * 16 + groupID;
            uint32_t ah[4], al[4];
            ah[0] = Ah[cur][row][tid4];
            ah[1] = Ah[cur][row + 8][tid4];
            ah[2] = Ah[cur][row][tid4 + 4];
            ah[3] = Ah[cur][row + 8][tid4 + 4];
            al[0] = Al[cur][row][tid4];
            al[1] = Al[cur][row + 8][tid4];
            al[2] = Al[cur][row][tid4 + 4];
            al[3] = Al[cur][row + 8][tid4 + 4];
#pragma unroll
            for (int nt = 0; nt < 8; nt++) {
                int n = warp_n * 64 + nt * 8 + groupID;
                uint32_t bh0 = Bh[cur][tid4][n];
                uint32_t bh1 = Bh[cur][tid4 + 4][n];
                uint32_t bl0 = Bl[cur][tid4][n];
                uint32_t bl1 = Bl[cur][tid4 + 4][n];
                mma_bf16(acc[nt], ah[0], ah[1], ah[2], ah[3], bh0, bh1);
                mma_bf16(acc[nt], al[0], al[1], al[2], al[3], bh0, bh1);
                mma_bf16(acc[nt], ah[0], ah[1], ah[2], ah[3], bl0, bl1);
            }
        }
        if (have_next) stash(cur ^ 1, av, bv0, bv1);
        __syncthreads();
    }

    // ---- store h1 (fp32) + fused alpha1 ----
    int head = (colBase >> 6) + warp_n;
    float ss[2] = {0.f, 0.f}, sd[2] = {0.f, 0.f};
    int row0 = rowBase + warp_m * 16 + groupID;
    int row1 = row0 + 8;
#pragma unroll
    for (int nt = 0; nt < 8; nt++) {
        int col = colBase + warp_n * 64 + nt * 8 + tid4 * 2;
        float a_s0 = att_s[col], a_s1 = att_s[col + 1];
        float a_d0 = att_d[col], a_d1 = att_d[col + 1];
        float c0 = acc[nt][0], c1 = acc[nt][1];
        float c2 = acc[nt][2], c3 = acc[nt][3];
        if (row0 < M) *(float2*)&g_h1[row0 * H1_DIM + col] = make_float2(c0, c1);
        if (row1 < M) *(float2*)&g_h1[row1 * H1_DIM + col] = make_float2(c2, c3);
        ss[0] = fmaf(c0, a_s0, fmaf(c1, a_s1, ss[0]));
        ss[1] = fmaf(c2, a_s0, fmaf(c3, a_s1, ss[1]));
        sd[0] = fmaf(c0, a_d0, fmaf(c1, a_d1, sd[0]));
        sd[1] = fmaf(c2, a_d0, fmaf(c3, a_d1, sd[1]));
    }
#pragma unroll
    for (int hf = 0; hf < 2; hf++) {
#pragma unroll
        for (int off = 1; off < 4; off <<= 1) {
            ss[hf] += __shfl_xor_sync(0xffffffffu, ss[hf], off);
            sd[hf] += __shfl_xor_sync(0xffffffffu, sd[hf], off);
        }
        if (tid4 == 0) {
            int row = rowBase + warp_m * 16 + groupID + hf * 8;
            if (row < M) {
                g_as1[row * HEADS + head] = ss[hf];
                g_ad1[row * HEADS + head] = sd[hf];
            }
        }
    }
}

// ---- fused L1 single-pass softmax + aggregate + bias + relu (block/dst) ----
// warp-per-edge gather: 8 warps in flight, 32 lanes x 8 fp32 channels
__global__ void k_agg1(const float* __restrict__ bias) {
    int n = blockIdx.x;
    int tid = threadIdx.x;
    int beg = g_rowptr[n];
    int deg = g_rowptr[n + 1] - beg;
    int lane = tid & 31, warp = tid >> 5;

    __shared__ int    sh_src[64];
    __shared__ float  sh_w[HEADS][64];
    __shared__ float4 sh_s[8];
    __shared__ float  sh_inv[HEADS];
    __shared__ float  sh_red[8][H1_DIM];   // 8 KB

    float4 ad4 = *(const float4*)&g_ad1[n * HEADS];

    int g = warp;                 // edge group = warp
    int cbase = lane * 8;         // 8 channels per lane
    int head = lane >> 3;
    float acc[8] = {};
    float4 sacc = make_float4(0.f, 0.f, 0.f, 0.f);

    for (int base = 0; base < deg; base += 64) {
        int len = min(64, deg - base);
        __syncthreads();
        if (tid < len) {
            int src = g_csr_src[beg + base + tid];
            sh_src[tid] = src;
            float4 as = *(const float4*)&g_as1[src * HEADS];
            float e0 = __expf(lrelu(as.x + ad4.x));
            float e1 = __expf(lrelu(as.y + ad4.y));
            float e2 = __expf(lrelu(as.z + ad4.z));
            float e3 = __expf(lrelu(as.w + ad4.w));
            sh_w[0][tid] = e0; sh_w[1][tid] = e1;
            sh_w[2][tid] = e2; sh_w[3][tid] = e3;
            sacc.x += e0; sacc.y += e1; sacc.z += e2; sacc.w += e3;
        }
        __syncthreads();
#pragma unroll 2
        for (int k = g; k < len; k += 8) {
            float w = sh_w[head][k];
            const float* hp = &g_h1[sh_src[k] * H1_DIM + cbase];
            float4 v0 = *(const float4*)hp;
            float4 v1 = *(const float4*)(hp + 4);
            acc[0] = fmaf(w, v0.x, acc[0]);
            acc[1] = fmaf(w, v0.y, acc[1]);
            acc[2] = fmaf(w, v0.z, acc[2]);
            acc[3] = fmaf(w, v0.w, acc[3]);
            acc[4] = fmaf(w, v1.x, acc[4]);
            acc[5] = fmaf(w, v1.y, acc[5]);
            acc[6] = fmaf(w, v1.z, acc[6]);
            acc[7] = fmaf(w, v1.w, acc[7]);
        }
    }
#pragma unroll
    for (int off = 16; off > 0; off >>= 1) {
        sacc.x += __shfl_xor_sync(0xffffffffu, sacc.x, off);
        sacc.y += __shfl_xor_sync(0xffffffffu, sacc.y, off);
        sacc.z += __shfl_xor_sync(0xffffffffu, sacc.z, off);
        sacc.w += __shfl_xor_sync(0xffffffffu, sacc.w, off);
    }
    if (lane == 0) sh_s[warp] = sacc;
    __syncthreads();
    if (tid == 0) {
        float4 s = sh_s[0];
#pragma unroll
        for (int w = 1; w < 8; w++) {
            s.x += sh_s[w].x; s.y += sh_s[w].y;
            s.z += sh_s[w].z; s.w += sh_s[w].w;
        }
        sh_inv[0] = 1.f / s.x; sh_inv[1] = 1.f / s.y;
        sh_inv[2] = 1.f / s.z; sh_inv[3] = 1.f / s.w;
    }
    *(float4*)&sh_red[g][cbase]     = make_float4(acc[0], acc[1], acc[2], acc[3]);
    *(float4*)&sh_red[g][cbase + 4] = make_float4(acc[4], acc[5], acc[6], acc[7]);
    __syncthreads();
    int c = tid;
    float v = 0.f;
#pragma unroll
    for (int gg = 0; gg < 8; gg++) v += sh_red[gg][c];
    v = v * sh_inv[c >> 6] + bias[c];
    g_out1[n * H1_DIM + c] = v > 0.f ? v : 0.f;
}

// ---------------- GEMM2 [N,256]x[256,40] + fused alpha2 ---------------------
// register-blocked: thread = (row, 5 cols); alpha2 via 8-lane shuffle
#define HRS 68   // hr row stride (floats): 16B-aligned, conflict-free

__global__ void k_gemm2(const float* __restrict__ W2,
                        const float* __restrict__ att_s,
                        const float* __restrict__ att_d, int M) {
    __shared__ float W2s[64 * OUT_DIM];   // 10 KB
    __shared__ float hr[32 * HRS];        // 8.5 KB
    int tid = threadIdx.x;
    int rowBase = blockIdx.x * 32;
    int r = tid >> 3;            // 0..31
    int c0 = (tid & 7) * 5;      // 0,5,...,35
    float acc[5] = {0.f, 0.f, 0.f, 0.f, 0.f};

    for (int k0 = 0; k0 < H1_DIM; k0 += 64) {
        for (int idx = tid; idx < 64 * OUT_DIM; idx += 256)
            W2s[idx] = W2[(k0 + idx / OUT_DIM) * OUT_DIM + idx % OUT_DIM];
        for (int f = tid; f < 512; f += 256) {
            int rr = f >> 4, c4 = f & 15;
            int row = rowBase + rr;
            float4 v = make_float4(0.f, 0.f, 0.f, 0.f);
            if (row < M) v = *(const float4*)&g_out1[row * H1_DIM + k0 + c4 * 4];
            *(float4*)&hr[rr * HRS + c4 * 4] = v;
        }
        __syncthreads();
#pragma unroll 4
        for (int k = 0; k < 64; k++) {
            float a = hr[r * HRS + k];
            const float* wrow = &W2s[k * OUT_DIM + c0];
            acc[0] = fmaf(a, wrow[0], acc[0]);
            acc[1] = fmaf(a, wrow[1], acc[1]);
            acc[2] = fmaf(a, wrow[2], acc[2]);
            acc[3] = fmaf(a, wrow[3], acc[3]);
            acc[4] = fmaf(a, wrow[4], acc[4]);
        }
        __syncthreads();
    }

    int row = rowBase + r;
    float ss = 0.f, sd = 0.f;
#pragma unroll
    for (int j = 0; j < 5; j++) {
        ss = fmaf(acc[j], att_s[c0 + j], ss);
        sd = fmaf(acc[j], att_d[c0 + j], sd);
    }
#pragma unroll
    for (int off = 1; off < 8; off <<= 1) {
        ss += __shfl_xor_sync(0xffffffffu, ss, off);
        sd += __shfl_xor_sync(0xffffffffu, sd, off);
    }
    if (row < M) {
#pragma unroll
        for (int j = 0; j < 5; j++) g_h2[row * OUT_DIM + c0 + j] = acc[j];
        if ((tid & 7) == 0) {
            g_as2[row] = ss;
            g_ad2[row] = sd;
        }
    }
}

// ---- fused L2 single-pass softmax + aggregate + bias + log_softmax ---------
__global__ void k_agg2(const float* __restrict__ bias, float* __restrict__ out) {
    int n = blockIdx.x;
    int tid = threadIdx.x;
    int beg = g_rowptr[n];
    int deg = g_rowptr[n + 1] - beg;
    int lane = tid & 31, warp = tid >> 5;

    __shared__ int   sh_src[64];
    __shared__ float sh_w[64];
    __shared__ float sh_s[4];
    __shared__ float sh_inv;
    __shared__ float sh_part[128];
    __shared__ float sh_row[OUT_DIM];
    __shared__ float sh_lse;

    float adn = g_ad2[n];

    int eo = tid >> 6, c = tid & 63;
    float acc = 0.f, sacc = 0.f;
    for (int base = 0; base < deg; base += 64) {
        int len = min(64, deg - base);
        __syncthreads();
        if (tid < len) {
            int src = g_csr_src[beg + base + tid];
            sh_src[tid] = src;
            float e = __expf(lrelu(g_as2[src] + adn));
            sh_w[tid] = e;
            sacc += e;
        }
        __syncthreads();
        if (c < OUT_DIM) {
            for (int k = eo; k < len; k += 2)
                acc = fmaf(sh_w[k], g_h2[sh_src[k] * OUT_DIM + c], acc);
        }
    }
#pragma unroll
    for (int off = 16; off > 0; off >>= 1)
        sacc += __shfl_xor_sync(0xffffffffu, sacc, off);
    if (lane == 0) sh_s[warp] = sacc;
    sh_part[tid] = acc;
    __syncthreads();
    if (tid == 0) sh_inv = 1.f / (sh_s[0] + sh_s[1] + sh_s[2] + sh_s[3]);
    __syncthreads();
    if (tid < OUT_DIM)
        sh_row[tid] = (sh_part[tid] + sh_part[tid + 64]) * sh_inv + bias[tid];
    __syncthreads();
    if (tid == 0) {
        float m = -1e30f;
#pragma unroll
        for (int k = 0; k < OUT_DIM; k++) m = fmaxf(m, sh_row[k]);
        float s = 0.f;
#pragma unroll
        for (int k = 0; k < OUT_DIM; k++) s += __expf(sh_row[k] - m);
        sh_lse = m + logf(s);
    }
    __syncthreads();
    if (tid < OUT_DIM) out[n * OUT_DIM + tid] = sh_row[tid] - sh_lse;
}

// ----------------------------------------------------------------------------
extern "C" void kernel_launch(void* const* d_in, const int* in_sizes, int n_in,
                              void* d_out, int out_size) {
    const float* x   = (const float*)d_in[0];
    const int*   ei  = (const int*)d_in[1];
    const float* W1  = (const float*)d_in[2];
    const float* as1 = (const float*)d_in[3];
    const float* ad1 = (const float*)d_in[4];
    const float* b1  = (const float*)d_in[5];
    const float* W2  = (const float*)d_in[6];
    const float* as2 = (const float*)d_in[7];
    const float* ad2 = (const float*)d_in[8];
    const float* b2  = (const float*)d_in[9];
    float* out = (float*)d_out;

    int N  = in_sizes[0] / IN_DIM;
    int E  = in_sizes[1] / 2;
    int ET = E + N;

    // CSR build
    k_deg<<<(E + 255) / 256, 256>>>(ei, E);
    k_scan<<<1, 1024>>>(N);
    k_scatter<<<(ET + 255) / 256, 256>>>(ei, E, ET);

    // layer 1
    {
        dim3 grid(H1_DIM / 128, (N + 63) / 64);
        k_gemm1<<<grid, 256>>>(x, W1, as1, ad1, N);
    }
    k_agg1<<<N, 256>>>(b1);

    // layer 2
    k_gemm2<<<(N + 31) / 32, 256>>>(W2, as2, ad2, N);
    k_agg2<<<N, 128>>>(b2, out);
}